// round 2
// baseline (speedup 1.0000x reference)
#include <cuda_runtime.h>
#include <cstddef>

#define N_AGENTS 8192
#define HIDDEN   256
#define MSG      128
#define KEY      64

// ---------------- scratch (no allocations allowed) ----------------
__device__ float g_msg[N_AGENTS * MSG];
__device__ float g_key[N_AGENTS * KEY];
__device__ float g_qry[N_AGENTS * KEY];
__device__ float g_S  [N_AGENTS];          // row sums of exp(scores); inverted in-place
__device__ float g_att[N_AGENTS * MSG];    // attended (unnormalized, then normalized)
__device__ float g_Gr [N_AGENTS * HIDDEN];
__device__ float g_Gz [N_AGENTS * HIDDEN];
__device__ float g_Gin[N_AGENTS * HIDDEN];
__device__ float g_Ghn[N_AGENTS * HIDDEN];

// ---------------- generic dual GEMM: C = A1@B1 + A2@B2 + bias ----------------
// A row-major [M,K], B row-major [K,N], C [M,N]. M%64==0, N%64==0, K%16==0.
__global__ __launch_bounds__(256) void gemm_dual(
    const float* __restrict__ A1, const float* __restrict__ B1, int K1,
    const float* __restrict__ A2, const float* __restrict__ B2, int K2,
    const float* __restrict__ bias, float* __restrict__ C, int N)
{
    __shared__ float As[16][68];
    __shared__ float Bs[16][64];
    const int tid = threadIdx.x;
    const int m0 = blockIdx.y * 64, n0 = blockIdx.x * 64;
    const int r4 = (tid >> 4) * 4, c4 = (tid & 15) * 4;
    float acc[4][4] = {};

    #pragma unroll
    for (int ph = 0; ph < 2; ph++) {
        const float* A = ph ? A2 : A1;
        const float* B = ph ? B2 : B1;
        const int    K = ph ? K2 : K1;
        for (int k0 = 0; k0 < K; k0 += 16) {
            __syncthreads();
            {   // A tile 64x16, transpose into As[k][m]
                int m = tid >> 2, kq = (tid & 3) * 4;
                float4 a = *(const float4*)&A[(size_t)(m0 + m) * K + k0 + kq];
                As[kq + 0][m] = a.x; As[kq + 1][m] = a.y;
                As[kq + 2][m] = a.z; As[kq + 3][m] = a.w;
            }
            {   // B tile 16x64 direct
                int kk = tid >> 4, cq = (tid & 15) * 4;
                *(float4*)&Bs[kk][cq] = *(const float4*)&B[(size_t)(k0 + kk) * N + n0 + cq];
            }
            __syncthreads();
            #pragma unroll
            for (int k = 0; k < 16; k++) {
                float4 a = *(float4*)&As[k][r4];
                float4 b = *(float4*)&Bs[k][c4];
                float av[4] = {a.x, a.y, a.z, a.w};
                float bv[4] = {b.x, b.y, b.z, b.w};
                #pragma unroll
                for (int i = 0; i < 4; i++)
                    #pragma unroll
                    for (int j = 0; j < 4; j++)
                        acc[i][j] += av[i] * bv[j];
            }
        }
    }
    float4 bv = bias ? *(const float4*)&bias[n0 + c4] : make_float4(0.f, 0.f, 0.f, 0.f);
    #pragma unroll
    for (int i = 0; i < 4; i++) {
        float4 o = make_float4(acc[i][0] + bv.x, acc[i][1] + bv.y,
                               acc[i][2] + bv.z, acc[i][3] + bv.w);
        *(float4*)&C[(size_t)(m0 + r4 + i) * N + n0 + c4] = o;
    }
}

// ---------------- fused attention kernel ----------------
// Each block owns 32 rows. For each 32-col tile: scores = Q@K^T/8, clip,
// E = exp (0 on diag), write E (unnormalized attn) to gmem, accumulate
// row sums and attended += E @ messages. One pass over all columns.
__global__ __launch_bounds__(256, 2) void attn_kernel(float* __restrict__ E_out)
{
    __shared__ float Qs[32][68];   // q rows, k-contig
    __shared__ float Ks[64][36];   // transposed: Ks[k][j]
    __shared__ float Ms[32][128];  // message tile
    __shared__ float Es[32][36];   // exp(scores) tile

    const int tid = threadIdx.x;
    const int i0  = blockIdx.x * 32;

    {   // load Q stripe once
        int r = tid >> 3, k0 = (tid & 7) * 8;
        *(float4*)&Qs[r][k0]     = *(const float4*)&g_qry[(size_t)(i0 + r) * KEY + k0];
        *(float4*)&Qs[r][k0 + 4] = *(const float4*)&g_qry[(size_t)(i0 + r) * KEY + k0 + 4];
    }

    const int si = tid >> 3;          // score row (0..31)
    const int sj = (tid & 7) * 4;     // score col base
    const int r0 = tid >> 4;          // attended rows r0, r0+16
    const int c0 = (tid & 15) * 8;    // attended col base

    float acc[2][8] = {};
    float rsum = 0.f;

    for (int jt = 0; jt < N_AGENTS; jt += 32) {
        __syncthreads();   // previous tile's Es/Ms/Ks fully consumed
        {   // K tile, transposed into Ks[k][j]
            int j = tid >> 3, kk = (tid & 7) * 8;
            float4 a = *(const float4*)&g_key[(size_t)(jt + j) * KEY + kk];
            float4 b = *(const float4*)&g_key[(size_t)(jt + j) * KEY + kk + 4];
            Ks[kk + 0][j] = a.x; Ks[kk + 1][j] = a.y; Ks[kk + 2][j] = a.z; Ks[kk + 3][j] = a.w;
            Ks[kk + 4][j] = b.x; Ks[kk + 5][j] = b.y; Ks[kk + 6][j] = b.z; Ks[kk + 7][j] = b.w;
        }
        {   // message tile
            int j = tid >> 3, cc = (tid & 7) * 16;
            #pragma unroll
            for (int v = 0; v < 4; v++)
                *(float4*)&Ms[j][cc + v * 4] =
                    *(const float4*)&g_msg[(size_t)(jt + j) * MSG + cc + v * 4];
        }
        __syncthreads();

        // ---- scores: each thread computes 4 scores (row si, cols sj..sj+3) ----
        float sA[4] = {};
        #pragma unroll
        for (int k4 = 0; k4 < KEY; k4 += 4) {
            float4 q = *(float4*)&Qs[si][k4];
            float qv[4] = {q.x, q.y, q.z, q.w};
            #pragma unroll
            for (int t = 0; t < 4; t++) {
                float4 kv = *(float4*)&Ks[k4 + t][sj];
                sA[0] += qv[t] * kv.x; sA[1] += qv[t] * kv.y;
                sA[2] += qv[t] * kv.z; sA[3] += qv[t] * kv.w;
            }
        }
        const int gi = i0 + si;
        float e[4];
        #pragma unroll
        for (int t = 0; t < 4; t++) {
            float s = sA[t] * 0.125f;                 // /sqrt(64)
            s = fminf(fmaxf(s, -20.f), 20.f);
            e[t] = (gi == jt + sj + t) ? 0.f : __expf(s);
            rsum += e[t];
        }
        float4 ev = make_float4(e[0], e[1], e[2], e[3]);
        *(float4*)&Es[si][sj] = ev;
        *(float4*)&E_out[(size_t)gi * N_AGENTS + jt + sj] = ev;   // unnormalized
        __syncthreads();

        // ---- attended += Es(32x32) @ Ms(32x128); thread: 2 rows x 8 cols ----
        #pragma unroll 8
        for (int j = 0; j < 32; j++) {
            float e0 = Es[r0][j];
            float e1 = Es[r0 + 16][j];
            float4 ma = *(float4*)&Ms[j][c0];
            float4 mb = *(float4*)&Ms[j][c0 + 4];
            float mv[8] = {ma.x, ma.y, ma.z, ma.w, mb.x, mb.y, mb.z, mb.w};
            #pragma unroll
            for (int c = 0; c < 8; c++) {
                acc[0][c] += e0 * mv[c];
                acc[1][c] += e1 * mv[c];
            }
        }
    }

    // reduce row sum across the 8 threads sharing row si (contiguous lanes)
    rsum += __shfl_xor_sync(0xFFFFFFFFu, rsum, 4);
    rsum += __shfl_xor_sync(0xFFFFFFFFu, rsum, 2);
    rsum += __shfl_xor_sync(0xFFFFFFFFu, rsum, 1);
    if ((tid & 7) == 0) g_S[i0 + si] = rsum;

    #pragma unroll
    for (int rr = 0; rr < 2; rr++) {
        int gr = i0 + r0 + rr * 16;
        *(float4*)&g_att[(size_t)gr * MSG + c0] =
            make_float4(acc[rr][0], acc[rr][1], acc[rr][2], acc[rr][3]);
        *(float4*)&g_att[(size_t)gr * MSG + c0 + 4] =
            make_float4(acc[rr][4], acc[rr][5], acc[rr][6], acc[rr][7]);
    }
}

// ---------------- small elementwise kernels ----------------
__global__ void inv_S_kernel()
{
    int i = blockIdx.x * blockDim.x + threadIdx.x;
    if (i < N_AGENTS) g_S[i] = 1.0f / g_S[i];
}

__global__ void norm_attended_kernel()
{
    int v = blockIdx.x * blockDim.x + threadIdx.x;   // float4 index, MSG/4=32 per row
    float inv = g_S[v >> 5];
    float4 a = ((const float4*)g_att)[v];
    a.x *= inv; a.y *= inv; a.z *= inv; a.w *= inv;
    ((float4*)g_att)[v] = a;
}

__global__ void norm_attn_kernel(float* __restrict__ E)
{
    int v = blockIdx.x * blockDim.x + threadIdx.x;   // float4 index, 2048 per row
    float inv = g_S[v >> 11];
    float4 a = ((const float4*)E)[v];
    a.x *= inv; a.y *= inv; a.z *= inv; a.w *= inv;
    ((float4*)E)[v] = a;
}

__device__ __forceinline__ float sigm(float x) { return 1.f / (1.f + __expf(-x)); }

__global__ void gru_final_kernel(const float* __restrict__ h, float* __restrict__ out)
{
    int v = blockIdx.x * blockDim.x + threadIdx.x;   // float4 index over N*HIDDEN/4
    float4 gr  = ((const float4*)g_Gr)[v];
    float4 gz  = ((const float4*)g_Gz)[v];
    float4 gin = ((const float4*)g_Gin)[v];
    float4 ghn = ((const float4*)g_Ghn)[v];
    float4 hh  = ((const float4*)h)[v];
    float4 o;
    {
        float r = sigm(gr.x), z = sigm(gz.x);
        float n = tanhf(gin.x + r * ghn.x);
        o.x = (1.f - z) * n + z * hh.x;
    }
    {
        float r = sigm(gr.y), z = sigm(gz.y);
        float n = tanhf(gin.y + r * ghn.y);
        o.y = (1.f - z) * n + z * hh.y;
    }
    {
        float r = sigm(gr.z), z = sigm(gz.z);
        float n = tanhf(gin.z + r * ghn.z);
        o.z = (1.f - z) * n + z * hh.z;
    }
    {
        float r = sigm(gr.w), z = sigm(gz.w);
        float n = tanhf(gin.w + r * ghn.w);
        o.w = (1.f - z) * n + z * hh.w;
    }
    ((float4*)out)[v] = o;
}

// ---------------- launch ----------------
extern "C" void kernel_launch(void* const* d_in, const int* in_sizes, int n_in,
                              void* d_out, int out_size)
{
    const float* h     = (const float*)d_in[0];
    const float* W_msg = (const float*)d_in[1];
    const float* b_msg = (const float*)d_in[2];
    const float* W_key = (const float*)d_in[3];
    const float* b_key = (const float*)d_in[4];
    const float* W_qry = (const float*)d_in[5];
    const float* b_qry = (const float*)d_in[6];
    const float* Wi_r  = (const float*)d_in[7];
    const float* bi_r  = (const float*)d_in[8];
    const float* Wi_z  = (const float*)d_in[9];
    const float* bi_z  = (const float*)d_in[10];
    const float* Wi_n  = (const float*)d_in[11];
    const float* bi_n  = (const float*)d_in[12];
    const float* Wh_r  = (const float*)d_in[13];
    const float* Wh_z  = (const float*)d_in[14];
    const float* Wh_n  = (const float*)d_in[15];
    const float* bh_n  = (const float*)d_in[16];

    float* out    = (float*)d_out;
    float* h_new  = out;                                   // [8192,256]
    float* attn   = out + (size_t)N_AGENTS * HIDDEN;       // [8192,8192]

    float *p_msg, *p_key, *p_qry, *p_att, *p_Gr, *p_Gz, *p_Gin, *p_Ghn;
    cudaGetSymbolAddress((void**)&p_msg, g_msg);
    cudaGetSymbolAddress((void**)&p_key, g_key);
    cudaGetSymbolAddress((void**)&p_qry, g_qry);
    cudaGetSymbolAddress((void**)&p_att, g_att);
    cudaGetSymbolAddress((void**)&p_Gr,  g_Gr);
    cudaGetSymbolAddress((void**)&p_Gz,  g_Gz);
    cudaGetSymbolAddress((void**)&p_Gin, g_Gin);
    cudaGetSymbolAddress((void**)&p_Ghn, g_Ghn);

    const dim3 gM(MSG / 64,    N_AGENTS / 64);
    const dim3 gK(KEY / 64,    N_AGENTS / 64);
    const dim3 gH(HIDDEN / 64, N_AGENTS / 64);

    // projections
    gemm_dual<<<gM, 256>>>(h, W_msg, HIDDEN, nullptr, nullptr, 0, b_msg, p_msg, MSG);
    gemm_dual<<<gK, 256>>>(h, W_key, HIDDEN, nullptr, nullptr, 0, b_key, p_key, KEY);
    gemm_dual<<<gK, 256>>>(h, W_qry, HIDDEN, nullptr, nullptr, 0, b_qry, p_qry, KEY);

    // fused scores + exp + rowsum + attended (writes unnormalized E into attn)
    attn_kernel<<<N_AGENTS / 32, 256>>>(attn);

    inv_S_kernel<<<N_AGENTS / 256, 256>>>();
    norm_attended_kernel<<<(N_AGENTS * MSG / 4) / 256, 256>>>();
    norm_attn_kernel<<<(int)(((size_t)N_AGENTS * N_AGENTS / 4) / 256), 256>>>(attn);

    // GRU gates
    gemm_dual<<<gH, 256>>>(p_att, Wi_r, MSG, h, Wh_r, HIDDEN, bi_r, p_Gr,  HIDDEN);
    gemm_dual<<<gH, 256>>>(p_att, Wi_z, MSG, h, Wh_z, HIDDEN, bi_z, p_Gz,  HIDDEN);
    gemm_dual<<<gH, 256>>>(p_att, Wi_n, MSG, nullptr, nullptr, 0, bi_n, p_Gin, HIDDEN);
    gemm_dual<<<gH, 256>>>(h,     Wh_n, HIDDEN, nullptr, nullptr, 0, bh_n, p_Ghn, HIDDEN);

    gru_final_kernel<<<(N_AGENTS * HIDDEN / 4) / 256, 256>>>(h, h_new);
}

// round 3
// speedup vs baseline: 3.8138x; 3.8138x over previous
#include <cuda_runtime.h>
#include <cstddef>

#define N_AGENTS 8192
#define HIDDEN   256
#define MSG      128
#define KEY      64
#define NSPLIT   4
#define COLS_PER_SPLIT (N_AGENTS / NSPLIT)   // 2048

// ---------------- scratch (no allocations allowed) ----------------
__device__ float g_msg[N_AGENTS * MSG];
__device__ float g_key[N_AGENTS * KEY];
__device__ float g_qry[N_AGENTS * KEY];
__device__ float g_S  [N_AGENTS];                        // 1/rowsum after inv_S
__device__ float g_S_part[NSPLIT * N_AGENTS];            // partial row sums
__device__ float g_att[N_AGENTS * MSG];                  // normalized attended
__device__ float g_att_part[NSPLIT * N_AGENTS * MSG];    // partial attended
__device__ float g_Gr [N_AGENTS * HIDDEN];
__device__ float g_Gz [N_AGENTS * HIDDEN];
__device__ float g_Gin[N_AGENTS * HIDDEN];
__device__ float g_Ghn[N_AGENTS * HIDDEN];

// ---------------- dual GEMM: C = A1@B1 + A2@B2 + bias ----------------
// Tile 128(M) x 64(N), 256 threads, 8x4 per thread. K%16==0, M%128==0, N%64==0.
__global__ __launch_bounds__(256) void gemm_dual(
    const float* __restrict__ A1, const float* __restrict__ B1, int K1,
    const float* __restrict__ A2, const float* __restrict__ B2, int K2,
    const float* __restrict__ bias, float* __restrict__ C, int N)
{
    __shared__ float As[16][132];   // k-major, padded
    __shared__ float Bs[16][64];
    const int tid = threadIdx.x;
    const int m0 = blockIdx.y * 128, n0 = blockIdx.x * 64;
    const int rg = tid >> 4;        // 0..15 -> rows rg*8..+8
    const int cg = tid & 15;        // 0..15 -> cols cg*4..+4
    float acc[8][4] = {};

    #pragma unroll
    for (int ph = 0; ph < 2; ph++) {
        const float* A = ph ? A2 : A1;
        const float* B = ph ? B2 : B1;
        const int    K = ph ? K2 : K1;
        for (int k0 = 0; k0 < K; k0 += 16) {
            __syncthreads();
            {   // A tile 128x16 -> transposed As[k][m]
                int m = tid >> 1, kq = (tid & 1) * 8;
                const float* src = &A[(size_t)(m0 + m) * K + k0 + kq];
                float4 a0 = *(const float4*)&src[0];
                float4 a1 = *(const float4*)&src[4];
                As[kq + 0][m] = a0.x; As[kq + 1][m] = a0.y;
                As[kq + 2][m] = a0.z; As[kq + 3][m] = a0.w;
                As[kq + 4][m] = a1.x; As[kq + 5][m] = a1.y;
                As[kq + 6][m] = a1.z; As[kq + 7][m] = a1.w;
            }
            {   // B tile 16x64 direct
                int kk = tid >> 4, cq = (tid & 15) * 4;
                *(float4*)&Bs[kk][cq] = *(const float4*)&B[(size_t)(k0 + kk) * N + n0 + cq];
            }
            __syncthreads();
            #pragma unroll
            for (int k = 0; k < 16; k++) {
                float4 a0 = *(float4*)&As[k][rg * 8];
                float4 a1 = *(float4*)&As[k][rg * 8 + 4];
                float4 b  = *(float4*)&Bs[k][cg * 4];
                float av[8] = {a0.x, a0.y, a0.z, a0.w, a1.x, a1.y, a1.z, a1.w};
                float bv[4] = {b.x, b.y, b.z, b.w};
                #pragma unroll
                for (int r = 0; r < 8; r++)
                    #pragma unroll
                    for (int c = 0; c < 4; c++)
                        acc[r][c] += av[r] * bv[c];
            }
        }
    }
    float4 bv = bias ? *(const float4*)&bias[n0 + cg * 4] : make_float4(0.f, 0.f, 0.f, 0.f);
    #pragma unroll
    for (int r = 0; r < 8; r++) {
        float4 o = make_float4(acc[r][0] + bv.x, acc[r][1] + bv.y,
                               acc[r][2] + bv.z, acc[r][3] + bv.w);
        *(float4*)&C[(size_t)(m0 + rg * 8 + r) * N + n0 + cg * 4] = o;
    }
}

// ---------------- fused attention kernel ----------------
// Block: 128 rows x 2048-column split. Per 64-col tile: E=exp(clip(QK^T/8)),
// diag->0, write unnormalized E to gmem + smem, accumulate row sums and
// attended += E@M. 8x4 score tile, 8x8 attended tile per thread.
__global__ __launch_bounds__(256, 1) void attn_kernel(float* __restrict__ E_out)
{
    extern __shared__ float sm[];
    float* Qs = sm;                         // [128][68]
    float* Ks = Qs + 128 * 68;              // [64][68]
    float* Ms = Ks + 64 * 68;               // [64][128]
    float* Es = Ms + 64 * 128;              // [128][68]

    const int tid   = threadIdx.x;
    const int i0    = blockIdx.y * 128;
    const int jbase = blockIdx.x * COLS_PER_SPLIT;
    const int rg = tid >> 4;                // 0..15 -> rows rg*8..+8
    const int cg = tid & 15;                // 0..15

    {   // load Q stripe 128x64 once
        int r = tid >> 1, kq = (tid & 1) * 32;
        const float* src = &g_qry[(size_t)(i0 + r) * KEY + kq];
        float* dst = &Qs[r * 68 + kq];
        #pragma unroll
        for (int v = 0; v < 8; v++)
            *(float4*)&dst[v * 4] = *(const float4*)&src[v * 4];
    }

    float att[8][8] = {};
    float rs[8] = {};

    for (int jt = 0; jt < COLS_PER_SPLIT; jt += 64) {
        __syncthreads();
        {   // K tile 64x64, row-major Ks[j][k]
            int j = tid >> 2, kq = (tid & 3) * 16;
            const float* src = &g_key[(size_t)(jbase + jt + j) * KEY + kq];
            float* dst = &Ks[j * 68 + kq];
            #pragma unroll
            for (int v = 0; v < 4; v++)
                *(float4*)&dst[v * 4] = *(const float4*)&src[v * 4];
        }
        {   // M tile 64x128
            int j = tid >> 2, cq = (tid & 3) * 32;
            const float* src = &g_msg[(size_t)(jbase + jt + j) * MSG + cq];
            float* dst = &Ms[j * 128 + cq];
            #pragma unroll
            for (int v = 0; v < 8; v++)
                *(float4*)&dst[v * 4] = *(const float4*)&src[v * 4];
        }
        __syncthreads();

        // ---- scores: rows rg*8..+8 x cols cg*4..+4 (dot products over KEY) ----
        float acc[8][4] = {};
        #pragma unroll
        for (int k4 = 0; k4 < KEY; k4 += 4) {
            float4 b0 = *(float4*)&Ks[(cg * 4 + 0) * 68 + k4];
            float4 b1 = *(float4*)&Ks[(cg * 4 + 1) * 68 + k4];
            float4 b2 = *(float4*)&Ks[(cg * 4 + 2) * 68 + k4];
            float4 b3 = *(float4*)&Ks[(cg * 4 + 3) * 68 + k4];
            #pragma unroll
            for (int r = 0; r < 8; r++) {
                float4 a = *(float4*)&Qs[(rg * 8 + r) * 68 + k4];
                acc[r][0] += a.x * b0.x + a.y * b0.y + a.z * b0.z + a.w * b0.w;
                acc[r][1] += a.x * b1.x + a.y * b1.y + a.z * b1.z + a.w * b1.w;
                acc[r][2] += a.x * b2.x + a.y * b2.y + a.z * b2.z + a.w * b2.w;
                acc[r][3] += a.x * b3.x + a.y * b3.y + a.z * b3.z + a.w * b3.w;
            }
        }
        #pragma unroll
        for (int r = 0; r < 8; r++) {
            const int gi = i0 + rg * 8 + r;
            float ev[4];
            #pragma unroll
            for (int c = 0; c < 4; c++) {
                float s = acc[r][c] * 0.125f;            // /sqrt(64)
                s = fminf(fmaxf(s, -20.f), 20.f);
                float e = __expf(s);
                if (gi == jbase + jt + cg * 4 + c) e = 0.f;
                ev[c] = e;
                rs[r] += e;
            }
            float4 evv = make_float4(ev[0], ev[1], ev[2], ev[3]);
            *(float4*)&Es[(rg * 8 + r) * 68 + cg * 4] = evv;
            *(float4*)&E_out[(size_t)gi * N_AGENTS + jbase + jt + cg * 4] = evv;
        }
        __syncthreads();

        // ---- attended: att[8][8] += Es(128x64) @ Ms(64x128) ----
        #pragma unroll 4
        for (int j = 0; j < 64; j++) {
            float4 m0 = *(float4*)&Ms[j * 128 + cg * 8];
            float4 m1 = *(float4*)&Ms[j * 128 + cg * 8 + 4];
            float mv[8] = {m0.x, m0.y, m0.z, m0.w, m1.x, m1.y, m1.z, m1.w};
            #pragma unroll
            for (int r = 0; r < 8; r++) {
                float e = Es[(rg * 8 + r) * 68 + j];
                #pragma unroll
                for (int c = 0; c < 8; c++)
                    att[r][c] += e * mv[c];
            }
        }
    }

    // row-sum reduce across the 16 threads (cg) sharing each row group
    #pragma unroll
    for (int r = 0; r < 8; r++) {
        float v = rs[r];
        v += __shfl_xor_sync(0xFFFFFFFFu, v, 8, 16);
        v += __shfl_xor_sync(0xFFFFFFFFu, v, 4, 16);
        v += __shfl_xor_sync(0xFFFFFFFFu, v, 2, 16);
        v += __shfl_xor_sync(0xFFFFFFFFu, v, 1, 16);
        if (cg == 0)
            g_S_part[(size_t)blockIdx.x * N_AGENTS + i0 + rg * 8 + r] = v;
    }

    // attended partials
    #pragma unroll
    for (int r = 0; r < 8; r++) {
        size_t base = ((size_t)blockIdx.x * N_AGENTS + i0 + rg * 8 + r) * MSG + cg * 8;
        *(float4*)&g_att_part[base]     = make_float4(att[r][0], att[r][1], att[r][2], att[r][3]);
        *(float4*)&g_att_part[base + 4] = make_float4(att[r][4], att[r][5], att[r][6], att[r][7]);
    }
}

// ---------------- small elementwise kernels ----------------
__global__ void inv_S_kernel()
{
    int i = blockIdx.x * blockDim.x + threadIdx.x;
    float s = g_S_part[i] + g_S_part[N_AGENTS + i]
            + g_S_part[2 * N_AGENTS + i] + g_S_part[3 * N_AGENTS + i];
    g_S[i] = 1.0f / s;
}

__global__ void norm_attended_kernel()
{
    int v = blockIdx.x * blockDim.x + threadIdx.x;   // float4 idx over N*MSG/4
    float inv = g_S[v >> 5];
    const size_t stride = (size_t)N_AGENTS * MSG / 4;
    float4 a = ((const float4*)g_att_part)[v];
    float4 b = ((const float4*)g_att_part)[v + stride];
    float4 c = ((const float4*)g_att_part)[v + 2 * stride];
    float4 d = ((const float4*)g_att_part)[v + 3 * stride];
    float4 o = make_float4((a.x + b.x + c.x + d.x) * inv,
                           (a.y + b.y + c.y + d.y) * inv,
                           (a.z + b.z + c.z + d.z) * inv,
                           (a.w + b.w + c.w + d.w) * inv);
    ((float4*)g_att)[v] = o;
}

__global__ void norm_attn_kernel(float* __restrict__ E)
{
    int v = blockIdx.x * blockDim.x + threadIdx.x;   // float4 idx, 2048 per row
    float inv = g_S[v >> 11];
    float4 a = ((const float4*)E)[v];
    a.x *= inv; a.y *= inv; a.z *= inv; a.w *= inv;
    ((float4*)E)[v] = a;
}

__device__ __forceinline__ float sigm(float x) { return 1.f / (1.f + __expf(-x)); }

__global__ void gru_final_kernel(const float* __restrict__ h, float* __restrict__ out)
{
    int v = blockIdx.x * blockDim.x + threadIdx.x;
    float4 gr  = ((const float4*)g_Gr)[v];
    float4 gz  = ((const float4*)g_Gz)[v];
    float4 gin = ((const float4*)g_Gin)[v];
    float4 ghn = ((const float4*)g_Ghn)[v];
    float4 hh  = ((const float4*)h)[v];
    float4 o;
    { float r = sigm(gr.x), z = sigm(gz.x); float n = tanhf(gin.x + r * ghn.x); o.x = (1.f - z) * n + z * hh.x; }
    { float r = sigm(gr.y), z = sigm(gz.y); float n = tanhf(gin.y + r * ghn.y); o.y = (1.f - z) * n + z * hh.y; }
    { float r = sigm(gr.z), z = sigm(gz.z); float n = tanhf(gin.z + r * ghn.z); o.z = (1.f - z) * n + z * hh.z; }
    { float r = sigm(gr.w), z = sigm(gz.w); float n = tanhf(gin.w + r * ghn.w); o.w = (1.f - z) * n + z * hh.w; }
    ((float4*)out)[v] = o;
}

// ---------------- launch ----------------
extern "C" void kernel_launch(void* const* d_in, const int* in_sizes, int n_in,
                              void* d_out, int out_size)
{
    const float* h     = (const float*)d_in[0];
    const float* W_msg = (const float*)d_in[1];
    const float* b_msg = (const float*)d_in[2];
    const float* W_key = (const float*)d_in[3];
    const float* b_key = (const float*)d_in[4];
    const float* W_qry = (const float*)d_in[5];
    const float* b_qry = (const float*)d_in[6];
    const float* Wi_r  = (const float*)d_in[7];
    const float* bi_r  = (const float*)d_in[8];
    const float* Wi_z  = (const float*)d_in[9];
    const float* bi_z  = (const float*)d_in[10];
    const float* Wi_n  = (const float*)d_in[11];
    const float* bi_n  = (const float*)d_in[12];
    const float* Wh_r  = (const float*)d_in[13];
    const float* Wh_z  = (const float*)d_in[14];
    const float* Wh_n  = (const float*)d_in[15];
    const float* bh_n  = (const float*)d_in[16];

    float* out    = (float*)d_out;
    float* h_new  = out;                                   // [8192,256]
    float* attn   = out + (size_t)N_AGENTS * HIDDEN;       // [8192,8192]

    float *p_msg, *p_key, *p_qry, *p_att, *p_Gr, *p_Gz, *p_Gin, *p_Ghn;
    cudaGetSymbolAddress((void**)&p_msg, g_msg);
    cudaGetSymbolAddress((void**)&p_key, g_key);
    cudaGetSymbolAddress((void**)&p_qry, g_qry);
    cudaGetSymbolAddress((void**)&p_att, g_att);
    cudaGetSymbolAddress((void**)&p_Gr,  g_Gr);
    cudaGetSymbolAddress((void**)&p_Gz,  g_Gz);
    cudaGetSymbolAddress((void**)&p_Gin, g_Gin);
    cudaGetSymbolAddress((void**)&p_Ghn, g_Ghn);

    static const int ATTN_SMEM = (128 * 68 + 64 * 68 + 64 * 128 + 128 * 68) * 4; // 119808
    cudaFuncSetAttribute(attn_kernel, cudaFuncAttributeMaxDynamicSharedMemorySize, ATTN_SMEM);

    const dim3 gM(MSG / 64,    N_AGENTS / 128);
    const dim3 gK(KEY / 64,    N_AGENTS / 128);
    const dim3 gH(HIDDEN / 64, N_AGENTS / 128);

    // projections
    gemm_dual<<<gM, 256>>>(h, W_msg, HIDDEN, nullptr, nullptr, 0, b_msg, p_msg, MSG);
    gemm_dual<<<gK, 256>>>(h, W_key, HIDDEN, nullptr, nullptr, 0, b_key, p_key, KEY);
    gemm_dual<<<gK, 256>>>(h, W_qry, HIDDEN, nullptr, nullptr, 0, b_qry, p_qry, KEY);

    // fused scores + exp + rowsum + attended partials
    attn_kernel<<<dim3(NSPLIT, N_AGENTS / 128), 256, ATTN_SMEM>>>(attn);

    inv_S_kernel<<<N_AGENTS / 256, 256>>>();
    norm_attended_kernel<<<(N_AGENTS * MSG / 4) / 256, 256>>>();
    norm_attn_kernel<<<(int)(((size_t)N_AGENTS * N_AGENTS / 4) / 256), 256>>>(attn);

    // GRU gates
    gemm_dual<<<gH, 256>>>(p_att, Wi_r, MSG, h, Wh_r, HIDDEN, bi_r, p_Gr,  HIDDEN);
    gemm_dual<<<gH, 256>>>(p_att, Wi_z, MSG, h, Wh_z, HIDDEN, bi_z, p_Gz,  HIDDEN);
    gemm_dual<<<gH, 256>>>(p_att, Wi_n, MSG, nullptr, nullptr, 0, bi_n, p_Gin, HIDDEN);
    gemm_dual<<<gH, 256>>>(h,     Wh_n, HIDDEN, nullptr, nullptr, 0, bh_n, p_Ghn, HIDDEN);

    gru_final_kernel<<<(N_AGENTS * HIDDEN / 4) / 256, 256>>>(h, h_new);
}

// round 5
// speedup vs baseline: 7.6888x; 2.0160x over previous
#include <cuda_runtime.h>
#include <cuda_bf16.h>
#include <cstddef>
#include <cstdint>

#define N_AGENTS 8192
#define HIDDEN   256
#define MSG      128
#define KEY      64
#define NSPLIT   4
#define COLS_PER_SPLIT (N_AGENTS / NSPLIT)   // 2048

// ---------------- scratch (no allocations allowed) ----------------
__device__ float g_msg[N_AGENTS * MSG];
__device__ float g_key[N_AGENTS * KEY];
__device__ float g_qry[N_AGENTS * KEY];
__device__ float g_S  [N_AGENTS];
__device__ float g_S_part[NSPLIT * N_AGENTS];
__device__ float g_att[N_AGENTS * MSG];
__device__ float g_att_part[NSPLIT * N_AGENTS * MSG];
__device__ float g_Gr [N_AGENTS * HIDDEN];
__device__ float g_Gz [N_AGENTS * HIDDEN];
__device__ float g_Gin[N_AGENTS * HIDDEN];
__device__ float g_Ghn[N_AGENTS * HIDDEN];

// bf16 hi/lo splits (Q pre-scaled by 0.125)
__device__ __align__(16) __nv_bfloat16 g_kh[N_AGENTS * KEY];
__device__ __align__(16) __nv_bfloat16 g_kl[N_AGENTS * KEY];
__device__ __align__(16) __nv_bfloat16 g_qh[N_AGENTS * KEY];
__device__ __align__(16) __nv_bfloat16 g_ql[N_AGENTS * KEY];
__device__ __align__(16) __nv_bfloat16 g_mTh[MSG * N_AGENTS];  // transposed messages
__device__ __align__(16) __nv_bfloat16 g_mTl[MSG * N_AGENTS];

// ---------------- PTX helpers (compute_103-safe: no "a" features) ----------------
__device__ __forceinline__ uint32_t smem_u32(const void* p) {
    uint32_t a;
    asm("{ .reg .u64 t; cvta.to.shared.u64 t, %1; cvt.u32.u64 %0, t; }" : "=r"(a) : "l"(p));
    return a;
}

#define LDSM_X4(r0, r1, r2, r3, addr) \
    asm volatile("ldmatrix.sync.aligned.m8n8.x4.shared.b16 {%0,%1,%2,%3}, [%4];" \
                 : "=r"(r0), "=r"(r1), "=r"(r2), "=r"(r3) : "r"(addr))

#define LDSM_X2(r0, r1, addr) \
    asm volatile("ldmatrix.sync.aligned.m8n8.x2.shared.b16 {%0,%1}, [%2];" \
                 : "=r"(r0), "=r"(r1) : "r"(addr))

#define MMA_BF16(C, A, B0, B1) \
    asm volatile("mma.sync.aligned.m16n8k16.row.col.f32.bf16.bf16.f32 " \
                 "{%0,%1,%2,%3}, {%4,%5,%6,%7}, {%8,%9}, {%0,%1,%2,%3};" \
                 : "+f"((C)[0]), "+f"((C)[1]), "+f"((C)[2]), "+f"((C)[3]) \
                 : "r"((A)[0]), "r"((A)[1]), "r"((A)[2]), "r"((A)[3]), \
                   "r"(B0), "r"(B1))

__device__ __forceinline__ uint32_t pack_bf(__nv_bfloat16 a, __nv_bfloat16 b) {
    return (uint32_t)__bfloat16_as_ushort(a) | ((uint32_t)__bfloat16_as_ushort(b) << 16);
}

// smem tile strides (bf16 elements); rows padded +16B for conflict-free ldmatrix
#define KSTR 72    // 64 bf16 data + 8 pad  (144 B row)
#define MSTR 136   // 128 bf16 data + 8 pad (272 B row)
#define O_KH  0
#define O_KL  (128 * KSTR)
#define O_MH  (2 * 128 * KSTR)
#define O_ML  (2 * 128 * KSTR + 128 * MSTR)
#define ATTN_SMEM ((2 * 128 * KSTR + 2 * 128 * MSTR) * 2)   // 106496 bytes

// ---------------- fused attention: mma.sync bf16 hi/lo (3-product) ----------------
// Block: 128 query rows x 2048-column split. Per 128-col j-tile:
//   S = Qh@Kh' + Qh@Kl' + Ql@Kh'   (Q prescaled by 1/8)
//   E = exp(clip(S)), diag->0, E written unnormalized to gmem,
//   ATT += Eh@Mh' + Eh@Ml' + El@Mh'  (E fragments built in registers from S frags)
__global__ __launch_bounds__(256, 1) void attn_mma_kernel(float* __restrict__ E_out)
{
    extern __shared__ __nv_bfloat16 sm[];
    __nv_bfloat16* Kh = sm + O_KH;
    __nv_bfloat16* Kl = sm + O_KL;
    __nv_bfloat16* Mh = sm + O_MH;
    __nv_bfloat16* Ml = sm + O_ML;

    const int tid  = threadIdx.x;
    const int w    = tid >> 5, lane = tid & 31;
    const int tr   = lane >> 2;       // 0..7
    const int tc   = lane & 3;        // 0..3
    const int row0 = w * 16;          // warp's row block within 128
    const int i0    = blockIdx.x * 128;
    const int jbase = blockIdx.y * COLS_PER_SPLIT;

    // ---- stage Q (hi/lo) into K buffers, build persistent A fragments ----
    #pragma unroll
    for (int it = 0; it < 4; it++) {
        int idx = tid + it * 256;
        int r = idx >> 3, ch = idx & 7;
        *(uint4*)&Kh[r * KSTR + ch * 8] = *(const uint4*)&g_qh[(size_t)(i0 + r) * KEY + ch * 8];
        *(uint4*)&Kl[r * KSTR + ch * 8] = *(const uint4*)&g_ql[(size_t)(i0 + r) * KEY + ch * 8];
    }
    __syncthreads();

    uint32_t qh[4][4], ql[4][4];
    {
        int octet = lane >> 3;
        int rr = row0 + (octet & 1) * 8 + (lane & 7);
        int kk = (octet >> 1) * 8;
        #pragma unroll
        for (int ks = 0; ks < 4; ks++) {
            uint32_t ah = smem_u32(&Kh[rr * KSTR + ks * 16 + kk]);
            uint32_t al = smem_u32(&Kl[rr * KSTR + ks * 16 + kk]);
            LDSM_X4(qh[ks][0], qh[ks][1], qh[ks][2], qh[ks][3], ah);
            LDSM_X4(ql[ks][0], ql[ks][1], ql[ks][2], ql[ks][3], al);
        }
    }

    float at[16][4];
    #pragma unroll
    for (int n = 0; n < 16; n++)
        #pragma unroll
        for (int q = 0; q < 4; q++) at[n][q] = 0.f;
    float rs0 = 0.f, rs1 = 0.f;

    const int gr0 = i0 + row0 + tr;
    const int gr1 = gr0 + 8;

    for (int jt = 0; jt < COLS_PER_SPLIT; jt += 128) {
        const size_t j0 = (size_t)(jbase + jt);
        __syncthreads();   // previous tile fully consumed
        #pragma unroll
        for (int it = 0; it < 4; it++) {
            int idx = tid + it * 256;
            int r = idx >> 3, ch = idx & 7;
            *(uint4*)&Kh[r * KSTR + ch * 8] = *(const uint4*)&g_kh[(j0 + r) * KEY + ch * 8];
            *(uint4*)&Kl[r * KSTR + ch * 8] = *(const uint4*)&g_kl[(j0 + r) * KEY + ch * 8];
        }
        #pragma unroll
        for (int it = 0; it < 8; it++) {
            int idx = tid + it * 256;
            int c = idx >> 4, ch = idx & 15;
            *(uint4*)&Mh[c * MSTR + ch * 8] = *(const uint4*)&g_mTh[(size_t)c * N_AGENTS + j0 + ch * 8];
            *(uint4*)&Ml[c * MSTR + ch * 8] = *(const uint4*)&g_mTl[(size_t)c * N_AGENTS + j0 + ch * 8];
        }
        __syncthreads();

        // ---- scores ----
        float cs[16][4];
        #pragma unroll
        for (int n = 0; n < 16; n++) {
            cs[n][0] = cs[n][1] = cs[n][2] = cs[n][3] = 0.f;
            int rn = n * 8 + (lane & 7);
            int ko = (lane >> 3) * 8;
            uint32_t bh[8], bl[8];
            uint32_t a0 = smem_u32(&Kh[rn * KSTR + ko]);
            uint32_t a1 = smem_u32(&Kh[rn * KSTR + 32 + ko]);
            uint32_t a2 = smem_u32(&Kl[rn * KSTR + ko]);
            uint32_t a3 = smem_u32(&Kl[rn * KSTR + 32 + ko]);
            LDSM_X4(bh[0], bh[1], bh[2], bh[3], a0);
            LDSM_X4(bh[4], bh[5], bh[6], bh[7], a1);
            LDSM_X4(bl[0], bl[1], bl[2], bl[3], a2);
            LDSM_X4(bl[4], bl[5], bl[6], bl[7], a3);
            #pragma unroll
            for (int ks = 0; ks < 4; ks++) {
                MMA_BF16(cs[n], qh[ks], bh[ks * 2], bh[ks * 2 + 1]);
                MMA_BF16(cs[n], qh[ks], bl[ks * 2], bl[ks * 2 + 1]);
                MMA_BF16(cs[n], ql[ks], bh[ks * 2], bh[ks * 2 + 1]);
            }
        }

        // ---- epilogue: clip, exp, diag, rowsum, write unnormalized E ----
        #pragma unroll
        for (int n = 0; n < 16; n++) {
            int gc = jbase + jt + n * 8 + tc * 2;
            float e0 = __expf(fminf(fmaxf(cs[n][0], -20.f), 20.f));
            float e1 = __expf(fminf(fmaxf(cs[n][1], -20.f), 20.f));
            float e2 = __expf(fminf(fmaxf(cs[n][2], -20.f), 20.f));
            float e3 = __expf(fminf(fmaxf(cs[n][3], -20.f), 20.f));
            if (gr0 == gc)     e0 = 0.f;
            if (gr0 == gc + 1) e1 = 0.f;
            if (gr1 == gc)     e2 = 0.f;
            if (gr1 == gc + 1) e3 = 0.f;
            rs0 += e0 + e1;
            rs1 += e2 + e3;
            cs[n][0] = e0; cs[n][1] = e1; cs[n][2] = e2; cs[n][3] = e3;
            *(float2*)&E_out[(size_t)gr0 * N_AGENTS + gc] = make_float2(e0, e1);
            *(float2*)&E_out[(size_t)gr1 * N_AGENTS + gc] = make_float2(e2, e3);
        }

        // ---- attended: ATT += Eh@Mh' + Eh@Ml' + El@Mh' ----
        #pragma unroll
        for (int kp = 0; kp < 8; kp++) {
            // build E hi/lo A-fragments from score C-fragments (register-only)
            uint32_t eh[4], el[4];
            #pragma unroll
            for (int q = 0; q < 4; q++) {
                float v0 = cs[2 * kp + (q >> 1)][(q & 1) * 2];
                float v1 = cs[2 * kp + (q >> 1)][(q & 1) * 2 + 1];
                // q: 0 -> (tile 2kp, rows lo c0,c1) ... map below fixes ordering
                (void)v0; (void)v1;
                eh[q] = 0; el[q] = 0;
            }
            {   // explicit mapping: a0=(r lo,k lo pair)=cs[2kp][0,1]; a1=(r hi)=cs[2kp][2,3];
                // a2=(r lo,k hi)=cs[2kp+1][0,1]; a3=cs[2kp+1][2,3]
                float s00 = cs[2 * kp][0],     s01 = cs[2 * kp][1];
                float s10 = cs[2 * kp][2],     s11 = cs[2 * kp][3];
                float s20 = cs[2 * kp + 1][0], s21 = cs[2 * kp + 1][1];
                float s30 = cs[2 * kp + 1][2], s31 = cs[2 * kp + 1][3];
                __nv_bfloat16 h00 = __float2bfloat16(s00), h01 = __float2bfloat16(s01);
                __nv_bfloat16 h10 = __float2bfloat16(s10), h11 = __float2bfloat16(s11);
                __nv_bfloat16 h20 = __float2bfloat16(s20), h21 = __float2bfloat16(s21);
                __nv_bfloat16 h30 = __float2bfloat16(s30), h31 = __float2bfloat16(s31);
                eh[0] = pack_bf(h00, h01); eh[1] = pack_bf(h10, h11);
                eh[2] = pack_bf(h20, h21); eh[3] = pack_bf(h30, h31);
                el[0] = pack_bf(__float2bfloat16(s00 - __bfloat162float(h00)),
                                __float2bfloat16(s01 - __bfloat162float(h01)));
                el[1] = pack_bf(__float2bfloat16(s10 - __bfloat162float(h10)),
                                __float2bfloat16(s11 - __bfloat162float(h11)));
                el[2] = pack_bf(__float2bfloat16(s20 - __bfloat162float(h20)),
                                __float2bfloat16(s21 - __bfloat162float(h21)));
                el[3] = pack_bf(__float2bfloat16(s30 - __bfloat162float(h30)),
                                __float2bfloat16(s31 - __bfloat162float(h31)));
            }
            #pragma unroll
            for (int n = 0; n < 16; n++) {
                int rn = n * 8 + (lane & 7);
                int jo = kp * 16 + ((lane >> 3) & 1) * 8;
                uint32_t mh0, mh1, ml0, ml1;
                LDSM_X2(mh0, mh1, smem_u32(&Mh[rn * MSTR + jo]));
                LDSM_X2(ml0, ml1, smem_u32(&Ml[rn * MSTR + jo]));
                MMA_BF16(at[n], eh, mh0, mh1);
                MMA_BF16(at[n], eh, ml0, ml1);
                MMA_BF16(at[n], el, mh0, mh1);
            }
        }
    }

    // ---- row sums (reduce over tc lanes) ----
    rs0 += __shfl_xor_sync(0xFFFFFFFFu, rs0, 1);
    rs0 += __shfl_xor_sync(0xFFFFFFFFu, rs0, 2);
    rs1 += __shfl_xor_sync(0xFFFFFFFFu, rs1, 1);
    rs1 += __shfl_xor_sync(0xFFFFFFFFu, rs1, 2);
    if (tc == 0) {
        g_S_part[(size_t)blockIdx.y * N_AGENTS + gr0] = rs0;
        g_S_part[(size_t)blockIdx.y * N_AGENTS + gr1] = rs1;
    }

    // ---- attended partials ----
    #pragma unroll
    for (int n = 0; n < 16; n++) {
        size_t b0 = ((size_t)blockIdx.y * N_AGENTS + gr0) * MSG + n * 8 + tc * 2;
        size_t b1 = ((size_t)blockIdx.y * N_AGENTS + gr1) * MSG + n * 8 + tc * 2;
        *(float2*)&g_att_part[b0] = make_float2(at[n][0], at[n][1]);
        *(float2*)&g_att_part[b1] = make_float2(at[n][2], at[n][3]);
    }
}

// ---------------- dual GEMM (fp32 SIMT, unchanged) ----------------
__global__ __launch_bounds__(256) void gemm_dual(
    const float* __restrict__ A1, const float* __restrict__ B1, int K1,
    const float* __restrict__ A2, const float* __restrict__ B2, int K2,
    const float* __restrict__ bias, float* __restrict__ C, int N)
{
    __shared__ float As[16][132];
    __shared__ float Bs[16][64];
    const int tid = threadIdx.x;
    const int m0 = blockIdx.y * 128, n0 = blockIdx.x * 64;
    const int rg = tid >> 4, cg = tid & 15;
    float acc[8][4] = {};

    #pragma unroll
    for (int phx = 0; phx < 2; phx++) {
        const float* A = phx ? A2 : A1;
        const float* B = phx ? B2 : B1;
        const int    K = phx ? K2 : K1;
        for (int k0 = 0; k0 < K; k0 += 16) {
            __syncthreads();
            {
                int m = tid >> 1, kq = (tid & 1) * 8;
                const float* src = &A[(size_t)(m0 + m) * K + k0 + kq];
                float4 a0 = *(const float4*)&src[0];
                float4 a1 = *(const float4*)&src[4];
                As[kq + 0][m] = a0.x; As[kq + 1][m] = a0.y;
                As[kq + 2][m] = a0.z; As[kq + 3][m] = a0.w;
                As[kq + 4][m] = a1.x; As[kq + 5][m] = a1.y;
                As[kq + 6][m] = a1.z; As[kq + 7][m] = a1.w;
            }
            {
                int kk = tid >> 4, cq = (tid & 15) * 4;
                *(float4*)&Bs[kk][cq] = *(const float4*)&B[(size_t)(k0 + kk) * N + n0 + cq];
            }
            __syncthreads();
            #pragma unroll
            for (int k = 0; k < 16; k++) {
                float4 a0 = *(float4*)&As[k][rg * 8];
                float4 a1 = *(float4*)&As[k][rg * 8 + 4];
                float4 b  = *(float4*)&Bs[k][cg * 4];
                float av[8] = {a0.x, a0.y, a0.z, a0.w, a1.x, a1.y, a1.z, a1.w};
                float bv[4] = {b.x, b.y, b.z, b.w};
                #pragma unroll
                for (int r = 0; r < 8; r++)
                    #pragma unroll
                    for (int c = 0; c < 4; c++)
                        acc[r][c] += av[r] * bv[c];
            }
        }
    }
    float4 bv = bias ? *(const float4*)&bias[n0 + cg * 4] : make_float4(0.f, 0.f, 0.f, 0.f);
    #pragma unroll
    for (int r = 0; r < 8; r++) {
        float4 o = make_float4(acc[r][0] + bv.x, acc[r][1] + bv.y,
                               acc[r][2] + bv.z, acc[r][3] + bv.w);
        *(float4*)&C[(size_t)(m0 + rg * 8 + r) * N + n0 + cg * 4] = o;
    }
}

// ---------------- converts ----------------
__global__ void split_qk_kernel()
{
    int i = blockIdx.x * blockDim.x + threadIdx.x;    // N*KEY
    float k = g_key[i];
    __nv_bfloat16 kh = __float2bfloat16(k);
    g_kh[i] = kh; g_kl[i] = __float2bfloat16(k - __bfloat162float(kh));
    float q = g_qry[i] * 0.125f;                      // fold 1/sqrt(KEY)
    __nv_bfloat16 qh = __float2bfloat16(q);
    g_qh[i] = qh; g_ql[i] = __float2bfloat16(q - __bfloat162float(qh));
}

__global__ void msgT_split_kernel()   // grid (N/32, MSG/32), block (32,8)
{
    __shared__ float t[32][33];
    int n0 = blockIdx.x * 32, m0 = blockIdx.y * 32;
    #pragma unroll
    for (int i = threadIdx.y; i < 32; i += 8)
        t[i][threadIdx.x] = g_msg[(size_t)(n0 + i) * MSG + m0 + threadIdx.x];
    __syncthreads();
    #pragma unroll
    for (int i = threadIdx.y; i < 32; i += 8) {
        float v = t[threadIdx.x][i];
        __nv_bfloat16 hi = __float2bfloat16(v);
        size_t o = (size_t)(m0 + i) * N_AGENTS + n0 + threadIdx.x;
        g_mTh[o] = hi;
        g_mTl[o] = __float2bfloat16(v - __bfloat162float(hi));
    }
}

// ---------------- small elementwise kernels ----------------
__global__ void inv_S_kernel()
{
    int i = blockIdx.x * blockDim.x + threadIdx.x;
    float s = g_S_part[i] + g_S_part[N_AGENTS + i]
            + g_S_part[2 * N_AGENTS + i] + g_S_part[3 * N_AGENTS + i];
    g_S[i] = 1.0f / s;
}

__global__ void norm_attended_kernel()
{
    int v = blockIdx.x * blockDim.x + threadIdx.x;
    float inv = g_S[v >> 5];
    const size_t stride = (size_t)N_AGENTS * MSG / 4;
    float4 a = ((const float4*)g_att_part)[v];
    float4 b = ((const float4*)g_att_part)[v + stride];
    float4 c = ((const float4*)g_att_part)[v + 2 * stride];
    float4 d = ((const float4*)g_att_part)[v + 3 * stride];
    ((float4*)g_att)[v] = make_float4((a.x + b.x + c.x + d.x) * inv,
                                      (a.y + b.y + c.y + d.y) * inv,
                                      (a.z + b.z + c.z + d.z) * inv,
                                      (a.w + b.w + c.w + d.w) * inv);
}

__global__ void norm_attn_kernel(float* __restrict__ E)
{
    int v = blockIdx.x * blockDim.x + threadIdx.x;
    float inv = g_S[v >> 11];
    float4 a = ((const float4*)E)[v];
    a.x *= inv; a.y *= inv; a.z *= inv; a.w *= inv;
    ((float4*)E)[v] = a;
}

__device__ __forceinline__ float sigm(float x) { return 1.f / (1.f + __expf(-x)); }

__global__ void gru_final_kernel(const float* __restrict__ h, float* __restrict__ out)
{
    int v = blockIdx.x * blockDim.x + threadIdx.x;
    float4 gr  = ((const float4*)g_Gr)[v];
    float4 gz  = ((const float4*)g_Gz)[v];
    float4 gin = ((const float4*)g_Gin)[v];
    float4 ghn = ((const float4*)g_Ghn)[v];
    float4 hh  = ((const float4*)h)[v];
    float4 o;
    { float r = sigm(gr.x), z = sigm(gz.x); float n = tanhf(gin.x + r * ghn.x); o.x = (1.f - z) * n + z * hh.x; }
    { float r = sigm(gr.y), z = sigm(gz.y); float n = tanhf(gin.y + r * ghn.y); o.y = (1.f - z) * n + z * hh.y; }
    { float r = sigm(gr.z), z = sigm(gz.z); float n = tanhf(gin.z + r * ghn.z); o.z = (1.f - z) * n + z * hh.z; }
    { float r = sigm(gr.w), z = sigm(gz.w); float n = tanhf(gin.w + r * ghn.w); o.w = (1.f - z) * n + z * hh.w; }
    ((float4*)out)[v] = o;
}

// ---------------- launch ----------------
extern "C" void kernel_launch(void* const* d_in, const int* in_sizes, int n_in,
                              void* d_out, int out_size)
{
    const float* h     = (const float*)d_in[0];
    const float* W_msg = (const float*)d_in[1];
    const float* b_msg = (const float*)d_in[2];
    const float* W_key = (const float*)d_in[3];
    const float* b_key = (const float*)d_in[4];
    const float* W_qry = (const float*)d_in[5];
    const float* b_qry = (const float*)d_in[6];
    const float* Wi_r  = (const float*)d_in[7];
    const float* bi_r  = (const float*)d_in[8];
    const float* Wi_z  = (const float*)d_in[9];
    const float* bi_z  = (const float*)d_in[10];
    const float* Wi_n  = (const float*)d_in[11];
    const float* bi_n  = (const float*)d_in[12];
    const float* Wh_r  = (const float*)d_in[13];
    const float* Wh_z  = (const float*)d_in[14];
    const float* Wh_n  = (const float*)d_in[15];
    const float* bh_n  = (const float*)d_in[16];

    float* out    = (float*)d_out;
    float* h_new  = out;
    float* attn   = out + (size_t)N_AGENTS * HIDDEN;

    float *p_msg, *p_key, *p_qry, *p_att, *p_Gr, *p_Gz, *p_Gin, *p_Ghn;
    cudaGetSymbolAddress((void**)&p_msg, g_msg);
    cudaGetSymbolAddress((void**)&p_key, g_key);
    cudaGetSymbolAddress((void**)&p_qry, g_qry);
    cudaGetSymbolAddress((void**)&p_att, g_att);
    cudaGetSymbolAddress((void**)&p_Gr,  g_Gr);
    cudaGetSymbolAddress((void**)&p_Gz,  g_Gz);
    cudaGetSymbolAddress((void**)&p_Gin, g_Gin);
    cudaGetSymbolAddress((void**)&p_Ghn, g_Ghn);

    cudaFuncSetAttribute(attn_mma_kernel, cudaFuncAttributeMaxDynamicSharedMemorySize, ATTN_SMEM);

    const dim3 gM(MSG / 64,    N_AGENTS / 128);
    const dim3 gK(KEY / 64,    N_AGENTS / 128);
    const dim3 gH(HIDDEN / 64, N_AGENTS / 128);

    // projections (fp32)
    gemm_dual<<<gM, 256>>>(h, W_msg, HIDDEN, nullptr, nullptr, 0, b_msg, p_msg, MSG);
    gemm_dual<<<gK, 256>>>(h, W_key, HIDDEN, nullptr, nullptr, 0, b_key, p_key, KEY);
    gemm_dual<<<gK, 256>>>(h, W_qry, HIDDEN, nullptr, nullptr, 0, b_qry, p_qry, KEY);

    // bf16 hi/lo splits (+ message transpose)
    split_qk_kernel<<<(N_AGENTS * KEY) / 256, 256>>>();
    msgT_split_kernel<<<dim3(N_AGENTS / 32, MSG / 32), dim3(32, 8)>>>();

    // fused tensor-core attention (mma.sync)
    attn_mma_kernel<<<dim3(N_AGENTS / 128, NSPLIT), 256, ATTN_SMEM>>>(attn);

    inv_S_kernel<<<N_AGENTS / 256, 256>>>();
    norm_attended_kernel<<<(N_AGENTS * MSG / 4) / 256, 256>>>();
    norm_attn_kernel<<<(int)(((size_t)N_AGENTS * N_AGENTS / 4) / 256), 256>>>(attn);

    // GRU gates
    gemm_dual<<<gH, 256>>>(p_att, Wi_r, MSG, h, Wh_r, HIDDEN, bi_r, p_Gr,  HIDDEN);
    gemm_dual<<<gH, 256>>>(p_att, Wi_z, MSG, h, Wh_z, HIDDEN, bi_z, p_Gz,  HIDDEN);
    gemm_dual<<<gH, 256>>>(p_att, Wi_n, MSG, nullptr, nullptr, 0, bi_n, p_Gin, HIDDEN);
    gemm_dual<<<gH, 256>>>(h,     Wh_n, HIDDEN, nullptr, nullptr, 0, bh_n, p_Ghn, HIDDEN);

    gru_final_kernel<<<(N_AGENTS * HIDDEN / 4) / 256, 256>>>(h, h_new);
}

// round 6
// speedup vs baseline: 8.9543x; 1.1646x over previous
#include <cuda_runtime.h>
#include <cuda_bf16.h>
#include <cstddef>
#include <cstdint>

#define N_AGENTS 8192
#define HIDDEN   256
#define MSG      128
#define KEY      64
#define NSPLIT   4
#define COLS_PER_SPLIT (N_AGENTS / NSPLIT)   // 2048

// ---------------- scratch (no allocations allowed) ----------------
__device__ float g_qkm[N_AGENTS * 256];              // msg|key|qry fused projection
__device__ float g_S  [N_AGENTS];
__device__ float g_S_part[NSPLIT * N_AGENTS];
__device__ float g_att_part[NSPLIT * N_AGENTS * MSG];
__device__ float g_GA[N_AGENTS * 768];               // att@Wi_cat + bias_i
__device__ float g_GB[N_AGENTS * 768];               // h@Wh_cat
__device__ float g_bias_p[256];
__device__ float g_bias_i[768];

// bf16 hi/lo splits
__device__ __align__(16) __nv_bfloat16 g_kh[N_AGENTS * KEY];
__device__ __align__(16) __nv_bfloat16 g_kl[N_AGENTS * KEY];
__device__ __align__(16) __nv_bfloat16 g_qh[N_AGENTS * KEY];   // prescaled by 1/8
__device__ __align__(16) __nv_bfloat16 g_ql[N_AGENTS * KEY];
__device__ __align__(16) __nv_bfloat16 g_mTh[MSG * N_AGENTS];  // transposed messages
__device__ __align__(16) __nv_bfloat16 g_mTl[MSG * N_AGENTS];
__device__ __align__(16) __nv_bfloat16 g_hh[N_AGENTS * HIDDEN];
__device__ __align__(16) __nv_bfloat16 g_hl[N_AGENTS * HIDDEN];
__device__ __align__(16) __nv_bfloat16 g_ath[N_AGENTS * MSG];  // normalized attended
__device__ __align__(16) __nv_bfloat16 g_atl[N_AGENTS * MSG];
// transposed/split weights: Bt[n][k]
__device__ __align__(16) __nv_bfloat16 g_Wp_h[256 * 256];
__device__ __align__(16) __nv_bfloat16 g_Wp_l[256 * 256];
__device__ __align__(16) __nv_bfloat16 g_Wi_h[768 * 128];
__device__ __align__(16) __nv_bfloat16 g_Wi_l[768 * 128];
__device__ __align__(16) __nv_bfloat16 g_Wh_h[768 * 256];
__device__ __align__(16) __nv_bfloat16 g_Wh_l[768 * 256];

// ---------------- PTX helpers (compute_103-safe) ----------------
__device__ __forceinline__ uint32_t smem_u32(const void* p) {
    uint32_t a;
    asm("{ .reg .u64 t; cvta.to.shared.u64 t, %1; cvt.u32.u64 %0, t; }" : "=r"(a) : "l"(p));
    return a;
}

#define LDSM_X4(r0, r1, r2, r3, addr) \
    asm volatile("ldmatrix.sync.aligned.m8n8.x4.shared.b16 {%0,%1,%2,%3}, [%4];" \
                 : "=r"(r0), "=r"(r1), "=r"(r2), "=r"(r3) : "r"(addr))

#define LDSM_X2(r0, r1, addr) \
    asm volatile("ldmatrix.sync.aligned.m8n8.x2.shared.b16 {%0,%1}, [%2];" \
                 : "=r"(r0), "=r"(r1) : "r"(addr))

#define MMA_BF16(C, A, B0, B1) \
    asm volatile("mma.sync.aligned.m16n8k16.row.col.f32.bf16.bf16.f32 " \
                 "{%0,%1,%2,%3}, {%4,%5,%6,%7}, {%8,%9}, {%0,%1,%2,%3};" \
                 : "+f"((C)[0]), "+f"((C)[1]), "+f"((C)[2]), "+f"((C)[3]) \
                 : "r"((A)[0]), "r"((A)[1]), "r"((A)[2]), "r"((A)[3]), \
                   "r"(B0), "r"(B1))

__device__ __forceinline__ uint32_t pack_bf(__nv_bfloat16 a, __nv_bfloat16 b) {
    return (uint32_t)__bfloat16_as_ushort(a) | ((uint32_t)__bfloat16_as_ushort(b) << 16);
}

// ---------------- fused attention (verified round-5 kernel, unchanged) ----------------
#define KSTR 72
#define MSTR 136
#define O_KH  0
#define O_KL  (128 * KSTR)
#define O_MH  (2 * 128 * KSTR)
#define O_ML  (2 * 128 * KSTR + 128 * MSTR)
#define ATTN_SMEM ((2 * 128 * KSTR + 2 * 128 * MSTR) * 2)   // 106496 bytes

__global__ __launch_bounds__(256, 1) void attn_mma_kernel(float* __restrict__ E_out)
{
    extern __shared__ __nv_bfloat16 sm[];
    __nv_bfloat16* Kh = sm + O_KH;
    __nv_bfloat16* Kl = sm + O_KL;
    __nv_bfloat16* Mh = sm + O_MH;
    __nv_bfloat16* Ml = sm + O_ML;

    const int tid  = threadIdx.x;
    const int w    = tid >> 5, lane = tid & 31;
    const int tr   = lane >> 2;
    const int tc   = lane & 3;
    const int row0 = w * 16;
    const int i0    = blockIdx.x * 128;
    const int jbase = blockIdx.y * COLS_PER_SPLIT;

    #pragma unroll
    for (int it = 0; it < 4; it++) {
        int idx = tid + it * 256;
        int r = idx >> 3, ch = idx & 7;
        *(uint4*)&Kh[r * KSTR + ch * 8] = *(const uint4*)&g_qh[(size_t)(i0 + r) * KEY + ch * 8];
        *(uint4*)&Kl[r * KSTR + ch * 8] = *(const uint4*)&g_ql[(size_t)(i0 + r) * KEY + ch * 8];
    }
    __syncthreads();

    uint32_t qh[4][4], ql[4][4];
    {
        int octet = lane >> 3;
        int rr = row0 + (octet & 1) * 8 + (lane & 7);
        int kk = (octet >> 1) * 8;
        #pragma unroll
        for (int ks = 0; ks < 4; ks++) {
            uint32_t ah = smem_u32(&Kh[rr * KSTR + ks * 16 + kk]);
            uint32_t al = smem_u32(&Kl[rr * KSTR + ks * 16 + kk]);
            LDSM_X4(qh[ks][0], qh[ks][1], qh[ks][2], qh[ks][3], ah);
            LDSM_X4(ql[ks][0], ql[ks][1], ql[ks][2], ql[ks][3], al);
        }
    }

    float at[16][4];
    #pragma unroll
    for (int n = 0; n < 16; n++)
        #pragma unroll
        for (int q = 0; q < 4; q++) at[n][q] = 0.f;
    float rs0 = 0.f, rs1 = 0.f;

    const int gr0 = i0 + row0 + tr;
    const int gr1 = gr0 + 8;

    for (int jt = 0; jt < COLS_PER_SPLIT; jt += 128) {
        const size_t j0 = (size_t)(jbase + jt);
        __syncthreads();
        #pragma unroll
        for (int it = 0; it < 4; it++) {
            int idx = tid + it * 256;
            int r = idx >> 3, ch = idx & 7;
            *(uint4*)&Kh[r * KSTR + ch * 8] = *(const uint4*)&g_kh[(j0 + r) * KEY + ch * 8];
            *(uint4*)&Kl[r * KSTR + ch * 8] = *(const uint4*)&g_kl[(j0 + r) * KEY + ch * 8];
        }
        #pragma unroll
        for (int it = 0; it < 8; it++) {
            int idx = tid + it * 256;
            int c = idx >> 4, ch = idx & 15;
            *(uint4*)&Mh[c * MSTR + ch * 8] = *(const uint4*)&g_mTh[(size_t)c * N_AGENTS + j0 + ch * 8];
            *(uint4*)&Ml[c * MSTR + ch * 8] = *(const uint4*)&g_mTl[(size_t)c * N_AGENTS + j0 + ch * 8];
        }
        __syncthreads();

        float cs[16][4];
        #pragma unroll
        for (int n = 0; n < 16; n++) {
            cs[n][0] = cs[n][1] = cs[n][2] = cs[n][3] = 0.f;
            int rn = n * 8 + (lane & 7);
            int ko = (lane >> 3) * 8;
            uint32_t bh[8], bl[8];
            uint32_t a0 = smem_u32(&Kh[rn * KSTR + ko]);
            uint32_t a1 = smem_u32(&Kh[rn * KSTR + 32 + ko]);
            uint32_t a2 = smem_u32(&Kl[rn * KSTR + ko]);
            uint32_t a3 = smem_u32(&Kl[rn * KSTR + 32 + ko]);
            LDSM_X4(bh[0], bh[1], bh[2], bh[3], a0);
            LDSM_X4(bh[4], bh[5], bh[6], bh[7], a1);
            LDSM_X4(bl[0], bl[1], bl[2], bl[3], a2);
            LDSM_X4(bl[4], bl[5], bl[6], bl[7], a3);
            #pragma unroll
            for (int ks = 0; ks < 4; ks++) {
                MMA_BF16(cs[n], qh[ks], bh[ks * 2], bh[ks * 2 + 1]);
                MMA_BF16(cs[n], qh[ks], bl[ks * 2], bl[ks * 2 + 1]);
                MMA_BF16(cs[n], ql[ks], bh[ks * 2], bh[ks * 2 + 1]);
            }
        }

        #pragma unroll
        for (int n = 0; n < 16; n++) {
            int gc = jbase + jt + n * 8 + tc * 2;
            float e0 = __expf(fminf(fmaxf(cs[n][0], -20.f), 20.f));
            float e1 = __expf(fminf(fmaxf(cs[n][1], -20.f), 20.f));
            float e2 = __expf(fminf(fmaxf(cs[n][2], -20.f), 20.f));
            float e3 = __expf(fminf(fmaxf(cs[n][3], -20.f), 20.f));
            if (gr0 == gc)     e0 = 0.f;
            if (gr0 == gc + 1) e1 = 0.f;
            if (gr1 == gc)     e2 = 0.f;
            if (gr1 == gc + 1) e3 = 0.f;
            rs0 += e0 + e1;
            rs1 += e2 + e3;
            cs[n][0] = e0; cs[n][1] = e1; cs[n][2] = e2; cs[n][3] = e3;
            *(float2*)&E_out[(size_t)gr0 * N_AGENTS + gc] = make_float2(e0, e1);
            *(float2*)&E_out[(size_t)gr1 * N_AGENTS + gc] = make_float2(e2, e3);
        }

        #pragma unroll
        for (int kp = 0; kp < 8; kp++) {
            uint32_t eh[4], el[4];
            {
                float s00 = cs[2 * kp][0],     s01 = cs[2 * kp][1];
                float s10 = cs[2 * kp][2],     s11 = cs[2 * kp][3];
                float s20 = cs[2 * kp + 1][0], s21 = cs[2 * kp + 1][1];
                float s30 = cs[2 * kp + 1][2], s31 = cs[2 * kp + 1][3];
                __nv_bfloat16 h00 = __float2bfloat16(s00), h01 = __float2bfloat16(s01);
                __nv_bfloat16 h10 = __float2bfloat16(s10), h11 = __float2bfloat16(s11);
                __nv_bfloat16 h20 = __float2bfloat16(s20), h21 = __float2bfloat16(s21);
                __nv_bfloat16 h30 = __float2bfloat16(s30), h31 = __float2bfloat16(s31);
                eh[0] = pack_bf(h00, h01); eh[1] = pack_bf(h10, h11);
                eh[2] = pack_bf(h20, h21); eh[3] = pack_bf(h30, h31);
                el[0] = pack_bf(__float2bfloat16(s00 - __bfloat162float(h00)),
                                __float2bfloat16(s01 - __bfloat162float(h01)));
                el[1] = pack_bf(__float2bfloat16(s10 - __bfloat162float(h10)),
                                __float2bfloat16(s11 - __bfloat162float(h11)));
                el[2] = pack_bf(__float2bfloat16(s20 - __bfloat162float(h20)),
                                __float2bfloat16(s21 - __bfloat162float(h21)));
                el[3] = pack_bf(__float2bfloat16(s30 - __bfloat162float(h30)),
                                __float2bfloat16(s31 - __bfloat162float(h31)));
            }
            #pragma unroll
            for (int n = 0; n < 16; n++) {
                int rn = n * 8 + (lane & 7);
                int jo = kp * 16 + ((lane >> 3) & 1) * 8;
                uint32_t mh0, mh1, ml0, ml1;
                LDSM_X2(mh0, mh1, smem_u32(&Mh[rn * MSTR + jo]));
                LDSM_X2(ml0, ml1, smem_u32(&Ml[rn * MSTR + jo]));
                MMA_BF16(at[n], eh, mh0, mh1);
                MMA_BF16(at[n], eh, ml0, ml1);
                MMA_BF16(at[n], el, mh0, mh1);
            }
        }
    }

    rs0 += __shfl_xor_sync(0xFFFFFFFFu, rs0, 1);
    rs0 += __shfl_xor_sync(0xFFFFFFFFu, rs0, 2);
    rs1 += __shfl_xor_sync(0xFFFFFFFFu, rs1, 1);
    rs1 += __shfl_xor_sync(0xFFFFFFFFu, rs1, 2);
    if (tc == 0) {
        g_S_part[(size_t)blockIdx.y * N_AGENTS + gr0] = rs0;
        g_S_part[(size_t)blockIdx.y * N_AGENTS + gr1] = rs1;
    }

    #pragma unroll
    for (int n = 0; n < 16; n++) {
        size_t b0 = ((size_t)blockIdx.y * N_AGENTS + gr0) * MSG + n * 8 + tc * 2;
        size_t b1 = ((size_t)blockIdx.y * N_AGENTS + gr1) * MSG + n * 8 + tc * 2;
        *(float2*)&g_att_part[b0] = make_float2(at[n][0], at[n][1]);
        *(float2*)&g_att_part[b1] = make_float2(at[n][2], at[n][3]);
    }
}

// ---------------- tensor-core GEMM: C[M,N] = A@B + bias ----------------
// A hi/lo [M,K] row-major bf16; Bt hi/lo [N,K] row-major bf16. Tile 128x128, K chunks 64.
#define GSTR 72
#define GEMM_SMEM (4 * 128 * GSTR * 2)   // 73728 bytes

__global__ __launch_bounds__(256, 1) void gemm_tc(
    const __nv_bfloat16* __restrict__ Ah, const __nv_bfloat16* __restrict__ Al,
    const __nv_bfloat16* __restrict__ Bh, const __nv_bfloat16* __restrict__ Bl,
    const float* __restrict__ bias, float* __restrict__ C, int K, int N)
{
    extern __shared__ __nv_bfloat16 gsm[];
    __nv_bfloat16* As_h = gsm;
    __nv_bfloat16* As_l = gsm + 128 * GSTR;
    __nv_bfloat16* Bs_h = gsm + 2 * 128 * GSTR;
    __nv_bfloat16* Bs_l = gsm + 3 * 128 * GSTR;

    const int tid = threadIdx.x, w = tid >> 5, lane = tid & 31;
    const int tr = lane >> 2, tc = lane & 3;
    const int row0 = w * 16;
    const int m0 = blockIdx.y * 128, n0 = blockIdx.x * 128;

    float at[16][4];
    #pragma unroll
    for (int n = 0; n < 16; n++)
        #pragma unroll
        for (int q = 0; q < 4; q++) at[n][q] = 0.f;

    for (int kc = 0; kc < K; kc += 64) {
        __syncthreads();
        #pragma unroll
        for (int it = 0; it < 4; it++) {
            int idx = tid + it * 256;
            int r = idx >> 3, ch = idx & 7;
            *(uint4*)&As_h[r * GSTR + ch * 8] = *(const uint4*)&Ah[(size_t)(m0 + r) * K + kc + ch * 8];
            *(uint4*)&As_l[r * GSTR + ch * 8] = *(const uint4*)&Al[(size_t)(m0 + r) * K + kc + ch * 8];
            *(uint4*)&Bs_h[r * GSTR + ch * 8] = *(const uint4*)&Bh[(size_t)(n0 + r) * K + kc + ch * 8];
            *(uint4*)&Bs_l[r * GSTR + ch * 8] = *(const uint4*)&Bl[(size_t)(n0 + r) * K + kc + ch * 8];
        }
        __syncthreads();

        uint32_t ah[4][4], al[4][4];
        {
            int octet = lane >> 3;
            int rr = row0 + (octet & 1) * 8 + (lane & 7);
            int kk = (octet >> 1) * 8;
            #pragma unroll
            for (int ks = 0; ks < 4; ks++) {
                LDSM_X4(ah[ks][0], ah[ks][1], ah[ks][2], ah[ks][3],
                        smem_u32(&As_h[rr * GSTR + ks * 16 + kk]));
                LDSM_X4(al[ks][0], al[ks][1], al[ks][2], al[ks][3],
                        smem_u32(&As_l[rr * GSTR + ks * 16 + kk]));
            }
        }
        #pragma unroll
        for (int np = 0; np < 8; np++) {
            int rn = np * 16 + ((lane >> 4) & 1) * 8 + (lane & 7);
            int ko = ((lane >> 3) & 1) * 8;
            #pragma unroll
            for (int ks = 0; ks < 4; ks++) {
                uint32_t bh0, bh1, bh2, bh3, bl0, bl1, bl2, bl3;
                LDSM_X4(bh0, bh1, bh2, bh3, smem_u32(&Bs_h[rn * GSTR + ks * 16 + ko]));
                LDSM_X4(bl0, bl1, bl2, bl3, smem_u32(&Bs_l[rn * GSTR + ks * 16 + ko]));
                MMA_BF16(at[2 * np],     ah[ks], bh0, bh1);
                MMA_BF16(at[2 * np],     ah[ks], bl0, bl1);
                MMA_BF16(at[2 * np],     al[ks], bh0, bh1);
                MMA_BF16(at[2 * np + 1], ah[ks], bh2, bh3);
                MMA_BF16(at[2 * np + 1], ah[ks], bl2, bl3);
                MMA_BF16(at[2 * np + 1], al[ks], bh2, bh3);
            }
        }
    }

    const int gr0 = m0 + row0 + tr, gr1 = gr0 + 8;
    #pragma unroll
    for (int n = 0; n < 16; n++) {
        int col = n0 + n * 8 + tc * 2;
        float b0 = bias ? bias[col] : 0.f;
        float b1 = bias ? bias[col + 1] : 0.f;
        *(float2*)&C[(size_t)gr0 * N + col] = make_float2(at[n][0] + b0, at[n][1] + b1);
        *(float2*)&C[(size_t)gr1 * N + col] = make_float2(at[n][2] + b0, at[n][3] + b1);
    }
}

// ---------------- prep kernels ----------------
__global__ void h_split_kernel(const float* __restrict__ h)
{
    int v = blockIdx.x * blockDim.x + threadIdx.x;   // float4 idx over N*HIDDEN/4
    float4 a = ((const float4*)h)[v];
    __nv_bfloat16 h0 = __float2bfloat16(a.x), h1 = __float2bfloat16(a.y);
    __nv_bfloat16 h2 = __float2bfloat16(a.z), h3 = __float2bfloat16(a.w);
    *(uint2*)&g_hh[4 * v] = make_uint2(pack_bf(h0, h1), pack_bf(h2, h3));
    *(uint2*)&g_hl[4 * v] = make_uint2(
        pack_bf(__float2bfloat16(a.x - __bfloat162float(h0)),
                __float2bfloat16(a.y - __bfloat162float(h1))),
        pack_bf(__float2bfloat16(a.z - __bfloat162float(h2)),
                __float2bfloat16(a.w - __bfloat162float(h3))));
}

__global__ void transpose_split_kernel(const float* __restrict__ src, int K, int N,
                                       __nv_bfloat16* __restrict__ dh,
                                       __nv_bfloat16* __restrict__ dl,
                                       int row_off, int Kd, float scale)
{
    int idx = blockIdx.x * blockDim.x + threadIdx.x;
    if (idx >= K * N) return;
    int k = idx / N, n = idx % N;
    float v = src[idx] * scale;
    __nv_bfloat16 hi = __float2bfloat16(v);
    size_t o = (size_t)(row_off + n) * Kd + k;
    dh[o] = hi;
    dl[o] = __float2bfloat16(v - __bfloat162float(hi));
}

__global__ void bias_cat_kernel(const float* b_msg, const float* b_key, const float* b_qry,
                                const float* bi_r, const float* bi_z, const float* bi_n)
{
    int i = threadIdx.x;   // 1024 threads
    if (i < 128)      g_bias_p[i] = b_msg[i];
    else if (i < 192) g_bias_p[i] = b_key[i - 128];
    else if (i < 256) g_bias_p[i] = 0.125f * b_qry[i - 192];
    if (i < 256)      g_bias_i[i] = bi_r[i];
    else if (i < 512) g_bias_i[i] = bi_z[i - 256];
    else if (i < 768) g_bias_i[i] = bi_n[i - 512];
}

__global__ void split_qk_kernel()
{
    int i = blockIdx.x * blockDim.x + threadIdx.x;   // over N*KEY
    int row = i >> 6, c = i & 63;
    float k = g_qkm[(size_t)row * 256 + 128 + c];
    __nv_bfloat16 kh = __float2bfloat16(k);
    g_kh[i] = kh; g_kl[i] = __float2bfloat16(k - __bfloat162float(kh));
    float q = g_qkm[(size_t)row * 256 + 192 + c];    // already scaled by 1/8
    __nv_bfloat16 qh = __float2bfloat16(q);
    g_qh[i] = qh; g_ql[i] = __float2bfloat16(q - __bfloat162float(qh));
}

__global__ void msgT_split_kernel()   // grid (N/32, MSG/32), block (32,8)
{
    __shared__ float t[32][33];
    int n0 = blockIdx.x * 32, m0 = blockIdx.y * 32;
    #pragma unroll
    for (int i = threadIdx.y; i < 32; i += 8)
        t[i][threadIdx.x] = g_qkm[(size_t)(n0 + i) * 256 + m0 + threadIdx.x];
    __syncthreads();
    #pragma unroll
    for (int i = threadIdx.y; i < 32; i += 8) {
        float v = t[threadIdx.x][i];
        __nv_bfloat16 hi = __float2bfloat16(v);
        size_t o = (size_t)(m0 + i) * N_AGENTS + n0 + threadIdx.x;
        g_mTh[o] = hi;
        g_mTl[o] = __float2bfloat16(v - __bfloat162float(hi));
    }
}

// ---------------- normalization / epilogue kernels ----------------
__global__ void inv_S_kernel()
{
    int i = blockIdx.x * blockDim.x + threadIdx.x;
    float s = g_S_part[i] + g_S_part[N_AGENTS + i]
            + g_S_part[2 * N_AGENTS + i] + g_S_part[3 * N_AGENTS + i];
    g_S[i] = 1.0f / s;
}

__global__ void norm_attended_kernel()   // writes bf16 hi/lo split of attended
{
    int v = blockIdx.x * blockDim.x + threadIdx.x;   // float4 idx over N*MSG/4
    float inv = g_S[v >> 5];
    const size_t stride = (size_t)N_AGENTS * MSG / 4;
    float4 a = ((const float4*)g_att_part)[v];
    float4 b = ((const float4*)g_att_part)[v + stride];
    float4 c = ((const float4*)g_att_part)[v + 2 * stride];
    float4 d = ((const float4*)g_att_part)[v + 3 * stride];
    float4 o = make_float4((a.x + b.x + c.x + d.x) * inv,
                           (a.y + b.y + c.y + d.y) * inv,
                           (a.z + b.z + c.z + d.z) * inv,
                           (a.w + b.w + c.w + d.w) * inv);
    __nv_bfloat16 h0 = __float2bfloat16(o.x), h1 = __float2bfloat16(o.y);
    __nv_bfloat16 h2 = __float2bfloat16(o.z), h3 = __float2bfloat16(o.w);
    *(uint2*)&g_ath[4 * v] = make_uint2(pack_bf(h0, h1), pack_bf(h2, h3));
    *(uint2*)&g_atl[4 * v] = make_uint2(
        pack_bf(__float2bfloat16(o.x - __bfloat162float(h0)),
                __float2bfloat16(o.y - __bfloat162float(h1))),
        pack_bf(__float2bfloat16(o.z - __bfloat162float(h2)),
                __float2bfloat16(o.w - __bfloat162float(h3))));
}

__global__ void norm_attn_kernel(float* __restrict__ E)
{
    int v = blockIdx.x * blockDim.x + threadIdx.x;
    float inv = g_S[v >> 11];
    float4 a = ((const float4*)E)[v];
    a.x *= inv; a.y *= inv; a.z *= inv; a.w *= inv;
    ((float4*)E)[v] = a;
}

__device__ __forceinline__ float sigm(float x) { return 1.f / (1.f + __expf(-x)); }

__global__ void gru_final_kernel(const float* __restrict__ h,
                                 const float* __restrict__ bh_n,
                                 float* __restrict__ out)
{
    int v = blockIdx.x * blockDim.x + threadIdx.x;   // float4 idx over N*HIDDEN/4
    int row = v >> 6, c4 = (v & 63) * 4;
    const float* GA = g_GA + (size_t)row * 768;
    const float* GB = g_GB + (size_t)row * 768;
    float4 gar = *(const float4*)&GA[c4];
    float4 gaz = *(const float4*)&GA[256 + c4];
    float4 gan = *(const float4*)&GA[512 + c4];
    float4 gbr = *(const float4*)&GB[c4];
    float4 gbz = *(const float4*)&GB[256 + c4];
    float4 gbn = *(const float4*)&GB[512 + c4];
    float4 bn  = *(const float4*)&bh_n[c4];
    float4 hh  = ((const float4*)h)[v];
    float4 o;
    { float r = sigm(gar.x + gbr.x), z = sigm(gaz.x + gbz.x);
      float n = tanhf(gan.x + r * (gbn.x + bn.x)); o.x = (1.f - z) * n + z * hh.x; }
    { float r = sigm(gar.y + gbr.y), z = sigm(gaz.y + gbz.y);
      float n = tanhf(gan.y + r * (gbn.y + bn.y)); o.y = (1.f - z) * n + z * hh.y; }
    { float r = sigm(gar.z + gbr.z), z = sigm(gaz.z + gbz.z);
      float n = tanhf(gan.z + r * (gbn.z + bn.z)); o.z = (1.f - z) * n + z * hh.z; }
    { float r = sigm(gar.w + gbr.w), z = sigm(gaz.w + gbz.w);
      float n = tanhf(gan.w + r * (gbn.w + bn.w)); o.w = (1.f - z) * n + z * hh.w; }
    ((float4*)out)[v] = o;
}

// ---------------- launch ----------------
extern "C" void kernel_launch(void* const* d_in, const int* in_sizes, int n_in,
                              void* d_out, int out_size)
{
    const float* h     = (const float*)d_in[0];
    const float* W_msg = (const float*)d_in[1];
    const float* b_msg = (const float*)d_in[2];
    const float* W_key = (const float*)d_in[3];
    const float* b_key = (const float*)d_in[4];
    const float* W_qry = (const float*)d_in[5];
    const float* b_qry = (const float*)d_in[6];
    const float* Wi_r  = (const float*)d_in[7];
    const float* bi_r  = (const float*)d_in[8];
    const float* Wi_z  = (const float*)d_in[9];
    const float* bi_z  = (const float*)d_in[10];
    const float* Wi_n  = (const float*)d_in[11];
    const float* bi_n  = (const float*)d_in[12];
    const float* Wh_r  = (const float*)d_in[13];
    const float* Wh_z  = (const float*)d_in[14];
    const float* Wh_n  = (const float*)d_in[15];
    const float* bh_n  = (const float*)d_in[16];

    float* out    = (float*)d_out;
    float* h_new  = out;
    float* attn   = out + (size_t)N_AGENTS * HIDDEN;

    float *p_qkm, *p_GA, *p_GB, *p_bias_p, *p_bias_i;
    __nv_bfloat16 *p_hh, *p_hl, *p_ath, *p_atl;
    __nv_bfloat16 *p_Wp_h, *p_Wp_l, *p_Wi_h, *p_Wi_l, *p_Wh_h, *p_Wh_l;
    cudaGetSymbolAddress((void**)&p_qkm, g_qkm);
    cudaGetSymbolAddress((void**)&p_GA, g_GA);
    cudaGetSymbolAddress((void**)&p_GB, g_GB);
    cudaGetSymbolAddress((void**)&p_bias_p, g_bias_p);
    cudaGetSymbolAddress((void**)&p_bias_i, g_bias_i);
    cudaGetSymbolAddress((void**)&p_hh, g_hh);
    cudaGetSymbolAddress((void**)&p_hl, g_hl);
    cudaGetSymbolAddress((void**)&p_ath, g_ath);
    cudaGetSymbolAddress((void**)&p_atl, g_atl);
    cudaGetSymbolAddress((void**)&p_Wp_h, g_Wp_h);
    cudaGetSymbolAddress((void**)&p_Wp_l, g_Wp_l);
    cudaGetSymbolAddress((void**)&p_Wi_h, g_Wi_h);
    cudaGetSymbolAddress((void**)&p_Wi_l, g_Wi_l);
    cudaGetSymbolAddress((void**)&p_Wh_h, g_Wh_h);
    cudaGetSymbolAddress((void**)&p_Wh_l, g_Wh_l);

    cudaFuncSetAttribute(attn_mma_kernel, cudaFuncAttributeMaxDynamicSharedMemorySize, ATTN_SMEM);
    cudaFuncSetAttribute(gemm_tc, cudaFuncAttributeMaxDynamicSharedMemorySize, GEMM_SMEM);

    // prep: splits + transposed/concatenated weights + biases
    h_split_kernel<<<(N_AGENTS * HIDDEN / 4) / 256, 256>>>(h);
    bias_cat_kernel<<<1, 1024>>>(b_msg, b_key, b_qry, bi_r, bi_z, bi_n);
    transpose_split_kernel<<<(256 * 128 + 255) / 256, 256>>>(W_msg, 256, 128, p_Wp_h, p_Wp_l, 0,   256, 1.0f);
    transpose_split_kernel<<<(256 * 64 + 255) / 256, 256>>>(W_key, 256, 64,  p_Wp_h, p_Wp_l, 128, 256, 1.0f);
    transpose_split_kernel<<<(256 * 64 + 255) / 256, 256>>>(W_qry, 256, 64,  p_Wp_h, p_Wp_l, 192, 256, 0.125f);
    transpose_split_kernel<<<(128 * 256 + 255) / 256, 256>>>(Wi_r, 128, 256, p_Wi_h, p_Wi_l, 0,   128, 1.0f);
    transpose_split_kernel<<<(128 * 256 + 255) / 256, 256>>>(Wi_z, 128, 256, p_Wi_h, p_Wi_l, 256, 128, 1.0f);
    transpose_split_kernel<<<(128 * 256 + 255) / 256, 256>>>(Wi_n, 128, 256, p_Wi_h, p_Wi_l, 512, 128, 1.0f);
    transpose_split_kernel<<<(256 * 256 + 255) / 256, 256>>>(Wh_r, 256, 256, p_Wh_h, p_Wh_l, 0,   256, 1.0f);
    transpose_split_kernel<<<(256 * 256 + 255) / 256, 256>>>(Wh_z, 256, 256, p_Wh_h, p_Wh_l, 256, 256, 1.0f);
    transpose_split_kernel<<<(256 * 256 + 255) / 256, 256>>>(Wh_n, 256, 256, p_Wh_h, p_Wh_l, 512, 256, 1.0f);

    // fused projection: qkm = h @ [W_msg | W_key | 0.125*W_qry] + bias
    gemm_tc<<<dim3(2, N_AGENTS / 128), 256, GEMM_SMEM>>>(
        p_hh, p_hl, p_Wp_h, p_Wp_l, p_bias_p, p_qkm, 256, 256);
    split_qk_kernel<<<(N_AGENTS * KEY) / 256, 256>>>();
    msgT_split_kernel<<<dim3(N_AGENTS / 32, MSG / 32), dim3(32, 8)>>>();

    // fused tensor-core attention
    attn_mma_kernel<<<dim3(N_AGENTS / 128, NSPLIT), 256, ATTN_SMEM>>>(attn);

    inv_S_kernel<<<N_AGENTS / 256, 256>>>();
    norm_attended_kernel<<<(N_AGENTS * MSG / 4) / 256, 256>>>();
    norm_attn_kernel<<<(int)(((size_t)N_AGENTS * N_AGENTS / 4) / 256), 256>>>(attn);

    // GRU gates: GA = att@Wi_cat + bias_i ; GB = h@Wh_cat
    gemm_tc<<<dim3(6, N_AGENTS / 128), 256, GEMM_SMEM>>>(
        p_ath, p_atl, p_Wi_h, p_Wi_l, p_bias_i, p_GA, 128, 768);
    gemm_tc<<<dim3(6, N_AGENTS / 128), 256, GEMM_SMEM>>>(
        p_hh, p_hl, p_Wh_h, p_Wh_l, nullptr, p_GB, 256, 768);

    gru_final_kernel<<<(N_AGENTS * HIDDEN / 4) / 256, 256>>>(h, bh_n, h_new);
}

// round 7
// speedup vs baseline: 9.0542x; 1.0112x over previous
#include <cuda_runtime.h>
#include <cuda_bf16.h>
#include <cstddef>
#include <cstdint>

#define N_AGENTS 8192
#define HIDDEN   256
#define MSG      128
#define KEY      64
#define NSPLIT   2
#define COLS_PER_SPLIT (N_AGENTS / NSPLIT)   // 4096
#define NT (COLS_PER_SPLIT / 128)            // 32 j-tiles per block

// ---------------- scratch (no allocations allowed) ----------------
__device__ float g_qkm[N_AGENTS * 256];              // msg|key|qry fused projection
__device__ float g_S  [N_AGENTS];
__device__ float g_S_part[NSPLIT * N_AGENTS];
__device__ float g_att_part[NSPLIT * N_AGENTS * MSG];
__device__ float g_GA[N_AGENTS * 768];
__device__ float g_GB[N_AGENTS * 768];
__device__ float g_bias_p[256];
__device__ float g_bias_i[768];

// bf16 hi/lo splits
__device__ __align__(16) __nv_bfloat16 g_kh[N_AGENTS * KEY];
__device__ __align__(16) __nv_bfloat16 g_kl[N_AGENTS * KEY];
__device__ __align__(16) __nv_bfloat16 g_qh[N_AGENTS * KEY];   // prescaled by 1/8
__device__ __align__(16) __nv_bfloat16 g_ql[N_AGENTS * KEY];
__device__ __align__(16) __nv_bfloat16 g_mTh[MSG * N_AGENTS];
__device__ __align__(16) __nv_bfloat16 g_mTl[MSG * N_AGENTS];
__device__ __align__(16) __nv_bfloat16 g_hh[N_AGENTS * HIDDEN];
__device__ __align__(16) __nv_bfloat16 g_hl[N_AGENTS * HIDDEN];
__device__ __align__(16) __nv_bfloat16 g_ath[N_AGENTS * MSG];
__device__ __align__(16) __nv_bfloat16 g_atl[N_AGENTS * MSG];
__device__ __align__(16) __nv_bfloat16 g_Wp_h[256 * 256];
__device__ __align__(16) __nv_bfloat16 g_Wp_l[256 * 256];
__device__ __align__(16) __nv_bfloat16 g_Wi_h[768 * 128];
__device__ __align__(16) __nv_bfloat16 g_Wi_l[768 * 128];
__device__ __align__(16) __nv_bfloat16 g_Wh_h[768 * 256];
__device__ __align__(16) __nv_bfloat16 g_Wh_l[768 * 256];

// ---------------- PTX helpers (compute_103-safe) ----------------
__device__ __forceinline__ uint32_t smem_u32(const void* p) {
    uint32_t a;
    asm("{ .reg .u64 t; cvta.to.shared.u64 t, %1; cvt.u32.u64 %0, t; }" : "=r"(a) : "l"(p));
    return a;
}

#define LDSM_X4(r0, r1, r2, r3, addr) \
    asm volatile("ldmatrix.sync.aligned.m8n8.x4.shared.b16 {%0,%1,%2,%3}, [%4];" \
                 : "=r"(r0), "=r"(r1), "=r"(r2), "=r"(r3) : "r"(addr))

#define LDSM_X2(r0, r1, addr) \
    asm volatile("ldmatrix.sync.aligned.m8n8.x2.shared.b16 {%0,%1}, [%2];" \
                 : "=r"(r0), "=r"(r1) : "r"(addr))

#define MMA_BF16(C, A, B0, B1) \
    asm volatile("mma.sync.aligned.m16n8k16.row.col.f32.bf16.bf16.f32 " \
                 "{%0,%1,%2,%3}, {%4,%5,%6,%7}, {%8,%9}, {%0,%1,%2,%3};" \
                 : "+f"((C)[0]), "+f"((C)[1]), "+f"((C)[2]), "+f"((C)[3]) \
                 : "r"((A)[0]), "r"((A)[1]), "r"((A)[2]), "r"((A)[3]), \
                   "r"(B0), "r"(B1))

#define CP16(smaddr, gptr) \
    asm volatile("cp.async.cg.shared.global [%0], [%1], 16;" :: "r"(smaddr), "l"(gptr) : "memory")
#define CP_COMMIT asm volatile("cp.async.commit_group;" ::: "memory")
#define CP_WAIT1  asm volatile("cp.async.wait_group 1;" ::: "memory")

__device__ __forceinline__ uint32_t pack_bf(__nv_bfloat16 a, __nv_bfloat16 b) {
    return (uint32_t)__bfloat16_as_ushort(a) | ((uint32_t)__bfloat16_as_ushort(b) << 16);
}

// ---------------- attention smem layout (2 pipeline stages) ----------------
#define KSTR 72    // 144 B rows (16B-aligned)
#define MSTR 136   // 272 B rows
#define S_KL (128 * KSTR)          // 9216
#define S_MH (2 * 128 * KSTR)      // 18432
#define S_ML (S_MH + 128 * MSTR)   // 35840
#define STAGE_ELEMS (2 * 128 * KSTR + 2 * 128 * MSTR)   // 53248 bf16
#define ATTN_SMEM (2 * STAGE_ELEMS * 2)                 // 212992 bytes

__device__ __forceinline__ void issue_tile(__nv_bfloat16* stage, size_t j0, int tid) {
    __nv_bfloat16* Kh = stage;
    __nv_bfloat16* Kl = stage + S_KL;
    __nv_bfloat16* Mh = stage + S_MH;
    __nv_bfloat16* Ml = stage + S_ML;
    #pragma unroll
    for (int it = 0; it < 4; it++) {
        int idx = tid + it * 256;
        int r = idx >> 3, ch = idx & 7;
        CP16(smem_u32(&Kh[r * KSTR + ch * 8]), &g_kh[(j0 + r) * KEY + ch * 8]);
        CP16(smem_u32(&Kl[r * KSTR + ch * 8]), &g_kl[(j0 + r) * KEY + ch * 8]);
    }
    #pragma unroll
    for (int it = 0; it < 8; it++) {
        int idx = tid + it * 256;
        int c = idx >> 4, ch = idx & 15;
        CP16(smem_u32(&Mh[c * MSTR + ch * 8]), &g_mTh[(size_t)c * N_AGENTS + j0 + ch * 8]);
        CP16(smem_u32(&Ml[c * MSTR + ch * 8]), &g_mTl[(size_t)c * N_AGENTS + j0 + ch * 8]);
    }
}

// ---------------- fused attention: mma.sync, cp.async double-buffered ----------------
__global__ __launch_bounds__(256, 1) void attn_mma_kernel(float* __restrict__ E_out)
{
    extern __shared__ __nv_bfloat16 sm[];
    __nv_bfloat16* st0 = sm;
    __nv_bfloat16* st1 = sm + STAGE_ELEMS;

    const int tid  = threadIdx.x;
    const int w    = tid >> 5, lane = tid & 31;
    const int tr   = lane >> 2;
    const int tc   = lane & 3;
    const int row0 = w * 16;
    const int i0    = blockIdx.x * 128;
    const int jbase = blockIdx.y * COLS_PER_SPLIT;

    // ---- stage Q (hi/lo) into stage0 K buffers, extract persistent fragments ----
    #pragma unroll
    for (int it = 0; it < 4; it++) {
        int idx = tid + it * 256;
        int r = idx >> 3, ch = idx & 7;
        *(uint4*)&st0[r * KSTR + ch * 8] =
            *(const uint4*)&g_qh[(size_t)(i0 + r) * KEY + ch * 8];
        *(uint4*)&st0[S_KL + r * KSTR + ch * 8] =
            *(const uint4*)&g_ql[(size_t)(i0 + r) * KEY + ch * 8];
    }
    __syncthreads();

    uint32_t qh[4][4], ql[4][4];
    {
        int octet = lane >> 3;
        int rr = row0 + (octet & 1) * 8 + (lane & 7);
        int kk = (octet >> 1) * 8;
        #pragma unroll
        for (int ks = 0; ks < 4; ks++) {
            LDSM_X4(qh[ks][0], qh[ks][1], qh[ks][2], qh[ks][3],
                    smem_u32(&st0[rr * KSTR + ks * 16 + kk]));
            LDSM_X4(ql[ks][0], ql[ks][1], ql[ks][2], ql[ks][3],
                    smem_u32(&st0[S_KL + rr * KSTR + ks * 16 + kk]));
        }
    }
    __syncthreads();

    // ---- pipeline prologue ----
    issue_tile(st0, (size_t)jbase, tid);       CP_COMMIT;
    issue_tile(st1, (size_t)jbase + 128, tid); CP_COMMIT;

    float at[16][4];
    #pragma unroll
    for (int n = 0; n < 16; n++)
        #pragma unroll
        for (int q = 0; q < 4; q++) at[n][q] = 0.f;
    float rs0 = 0.f, rs1 = 0.f;

    const int gr0 = i0 + row0 + tr;
    const int gr1 = gr0 + 8;

    for (int t = 0; t < NT; t++) {
        CP_WAIT1;
        __syncthreads();
        __nv_bfloat16* stage = (t & 1) ? st1 : st0;
        __nv_bfloat16* Kh = stage;
        __nv_bfloat16* Kl = stage + S_KL;
        __nv_bfloat16* Mh = stage + S_MH;
        __nv_bfloat16* Ml = stage + S_ML;
        const int jt = t * 128;

        // ---- scores: S = Qh@Kh' + Qh@Kl' + Ql@Kh' ----
        float cs[16][4];
        #pragma unroll
        for (int n = 0; n < 16; n++) {
            cs[n][0] = cs[n][1] = cs[n][2] = cs[n][3] = 0.f;
            int rn = n * 8 + (lane & 7);
            int ko = (lane >> 3) * 8;
            uint32_t bh[8], bl[8];
            LDSM_X4(bh[0], bh[1], bh[2], bh[3], smem_u32(&Kh[rn * KSTR + ko]));
            LDSM_X4(bh[4], bh[5], bh[6], bh[7], smem_u32(&Kh[rn * KSTR + 32 + ko]));
            LDSM_X4(bl[0], bl[1], bl[2], bl[3], smem_u32(&Kl[rn * KSTR + ko]));
            LDSM_X4(bl[4], bl[5], bl[6], bl[7], smem_u32(&Kl[rn * KSTR + 32 + ko]));
            #pragma unroll
            for (int ks = 0; ks < 4; ks++) {
                MMA_BF16(cs[n], qh[ks], bh[ks * 2], bh[ks * 2 + 1]);
                MMA_BF16(cs[n], qh[ks], bl[ks * 2], bl[ks * 2 + 1]);
                MMA_BF16(cs[n], ql[ks], bh[ks * 2], bh[ks * 2 + 1]);
            }
        }

        // ---- epilogue: clip, exp, diag, rowsum, write unnormalized E ----
        #pragma unroll
        for (int n = 0; n < 16; n++) {
            int gc = jbase + jt + n * 8 + tc * 2;
            float e0 = __expf(fminf(fmaxf(cs[n][0], -20.f), 20.f));
            float e1 = __expf(fminf(fmaxf(cs[n][1], -20.f), 20.f));
            float e2 = __expf(fminf(fmaxf(cs[n][2], -20.f), 20.f));
            float e3 = __expf(fminf(fmaxf(cs[n][3], -20.f), 20.f));
            if (gr0 == gc)     e0 = 0.f;
            if (gr0 == gc + 1) e1 = 0.f;
            if (gr1 == gc)     e2 = 0.f;
            if (gr1 == gc + 1) e3 = 0.f;
            rs0 += e0 + e1;
            rs1 += e2 + e3;
            cs[n][0] = e0; cs[n][1] = e1; cs[n][2] = e2; cs[n][3] = e3;
            *(float2*)&E_out[(size_t)gr0 * N_AGENTS + gc] = make_float2(e0, e1);
            *(float2*)&E_out[(size_t)gr1 * N_AGENTS + gc] = make_float2(e2, e3);
        }

        // ---- attended: ATT += Eh@Mh' + Eh@Ml' + El@Mh' ----
        #pragma unroll
        for (int kp = 0; kp < 8; kp++) {
            uint32_t eh[4], el[4];
            {
                float s00 = cs[2 * kp][0],     s01 = cs[2 * kp][1];
                float s10 = cs[2 * kp][2],     s11 = cs[2 * kp][3];
                float s20 = cs[2 * kp + 1][0], s21 = cs[2 * kp + 1][1];
                float s30 = cs[2 * kp + 1][2], s31 = cs[2 * kp + 1][3];
                __nv_bfloat16 h00 = __float2bfloat16(s00), h01 = __float2bfloat16(s01);
                __nv_bfloat16 h10 = __float2bfloat16(s10), h11 = __float2bfloat16(s11);
                __nv_bfloat16 h20 = __float2bfloat16(s20), h21 = __float2bfloat16(s21);
                __nv_bfloat16 h30 = __float2bfloat16(s30), h31 = __float2bfloat16(s31);
                eh[0] = pack_bf(h00, h01); eh[1] = pack_bf(h10, h11);
                eh[2] = pack_bf(h20, h21); eh[3] = pack_bf(h30, h31);
                el[0] = pack_bf(__float2bfloat16(s00 - __bfloat162float(h00)),
                                __float2bfloat16(s01 - __bfloat162float(h01)));
                el[1] = pack_bf(__float2bfloat16(s10 - __bfloat162float(h10)),
                                __float2bfloat16(s11 - __bfloat162float(h11)));
                el[2] = pack_bf(__float2bfloat16(s20 - __bfloat162float(h20)),
                                __float2bfloat16(s21 - __bfloat162float(h21)));
                el[3] = pack_bf(__float2bfloat16(s30 - __bfloat162float(h30)),
                                __float2bfloat16(s31 - __bfloat162float(h31)));
            }
            #pragma unroll
            for (int n = 0; n < 16; n++) {
                int rn = n * 8 + (lane & 7);
                int jo = kp * 16 + ((lane >> 3) & 1) * 8;
                uint32_t mh0, mh1, ml0, ml1;
                LDSM_X2(mh0, mh1, smem_u32(&Mh[rn * MSTR + jo]));
                LDSM_X2(ml0, ml1, smem_u32(&Ml[rn * MSTR + jo]));
                MMA_BF16(at[n], eh, mh0, mh1);
                MMA_BF16(at[n], eh, ml0, ml1);
                MMA_BF16(at[n], el, mh0, mh1);
            }
        }

        __syncthreads();
        if (t + 2 < NT)
            issue_tile((t & 1) ? st1 : st0, (size_t)jbase + (size_t)(t + 2) * 128, tid);
        CP_COMMIT;
    }

    rs0 += __shfl_xor_sync(0xFFFFFFFFu, rs0, 1);
    rs0 += __shfl_xor_sync(0xFFFFFFFFu, rs0, 2);
    rs1 += __shfl_xor_sync(0xFFFFFFFFu, rs1, 1);
    rs1 += __shfl_xor_sync(0xFFFFFFFFu, rs1, 2);
    if (tc == 0) {
        g_S_part[(size_t)blockIdx.y * N_AGENTS + gr0] = rs0;
        g_S_part[(size_t)blockIdx.y * N_AGENTS + gr1] = rs1;
    }

    #pragma unroll
    for (int n = 0; n < 16; n++) {
        size_t b0 = ((size_t)blockIdx.y * N_AGENTS + gr0) * MSG + n * 8 + tc * 2;
        size_t b1 = ((size_t)blockIdx.y * N_AGENTS + gr1) * MSG + n * 8 + tc * 2;
        *(float2*)&g_att_part[b0] = make_float2(at[n][0], at[n][1]);
        *(float2*)&g_att_part[b1] = make_float2(at[n][2], at[n][3]);
    }
}

// ---------------- tensor-core GEMM: C[M,N] = A@B + bias, double-buffered ----------------
#define GSTR 72
#define G_AL (128 * GSTR)
#define G_BH (2 * 128 * GSTR)
#define G_BL (3 * 128 * GSTR)
#define GSTAGE (4 * 128 * GSTR)            // elements per stage
#define GEMM_SMEM (2 * GSTAGE * 2)         // 147456 bytes

__device__ __forceinline__ void gemm_issue(
    __nv_bfloat16* stage,
    const __nv_bfloat16* Ah, const __nv_bfloat16* Al,
    const __nv_bfloat16* Bh, const __nv_bfloat16* Bl,
    int m0, int n0, int kc, int K, int tid)
{
    #pragma unroll
    for (int it = 0; it < 4; it++) {
        int idx = tid + it * 256;
        int r = idx >> 3, ch = idx & 7;
        CP16(smem_u32(&stage[r * GSTR + ch * 8]),        &Ah[(size_t)(m0 + r) * K + kc + ch * 8]);
        CP16(smem_u32(&stage[G_AL + r * GSTR + ch * 8]), &Al[(size_t)(m0 + r) * K + kc + ch * 8]);
        CP16(smem_u32(&stage[G_BH + r * GSTR + ch * 8]), &Bh[(size_t)(n0 + r) * K + kc + ch * 8]);
        CP16(smem_u32(&stage[G_BL + r * GSTR + ch * 8]), &Bl[(size_t)(n0 + r) * K + kc + ch * 8]);
    }
}

__global__ __launch_bounds__(256, 1) void gemm_tc(
    const __nv_bfloat16* __restrict__ Ah, const __nv_bfloat16* __restrict__ Al,
    const __nv_bfloat16* __restrict__ Bh, const __nv_bfloat16* __restrict__ Bl,
    const float* __restrict__ bias, float* __restrict__ C, int K, int N)
{
    extern __shared__ __nv_bfloat16 gsm[];
    __nv_bfloat16* gst[2] = { gsm, gsm + GSTAGE };

    const int tid = threadIdx.x, w = tid >> 5, lane = tid & 31;
    const int tr = lane >> 2, tc = lane & 3;
    const int row0 = w * 16;
    const int m0 = blockIdx.y * 128, n0 = blockIdx.x * 128;
    const int NK = K >> 6;

    gemm_issue(gst[0], Ah, Al, Bh, Bl, m0, n0, 0, K, tid);  CP_COMMIT;
    if (NK > 1) gemm_issue(gst[1], Ah, Al, Bh, Bl, m0, n0, 64, K, tid);
    CP_COMMIT;

    float at[16][4];
    #pragma unroll
    for (int n = 0; n < 16; n++)
        #pragma unroll
        for (int q = 0; q < 4; q++) at[n][q] = 0.f;

    for (int ki = 0; ki < NK; ki++) {
        CP_WAIT1;
        __syncthreads();
        __nv_bfloat16* stage = gst[ki & 1];

        uint32_t ah[4][4], al[4][4];
        {
            int octet = lane >> 3;
            int rr = row0 + (octet & 1) * 8 + (lane & 7);
            int kk = (octet >> 1) * 8;
            #pragma unroll
            for (int ks = 0; ks < 4; ks++) {
                LDSM_X4(ah[ks][0], ah[ks][1], ah[ks][2], ah[ks][3],
                        smem_u32(&stage[rr * GSTR + ks * 16 + kk]));
                LDSM_X4(al[ks][0], al[ks][1], al[ks][2], al[ks][3],
                        smem_u32(&stage[G_AL + rr * GSTR + ks * 16 + kk]));
            }
        }
        #pragma unroll
        for (int np = 0; np < 8; np++) {
            int rn = np * 16 + ((lane >> 4) & 1) * 8 + (lane & 7);
            int ko = ((lane >> 3) & 1) * 8;
            #pragma unroll
            for (int ks = 0; ks < 4; ks++) {
                uint32_t bh0, bh1, bh2, bh3, bl0, bl1, bl2, bl3;
                LDSM_X4(bh0, bh1, bh2, bh3, smem_u32(&stage[G_BH + rn * GSTR + ks * 16 + ko]));
                LDSM_X4(bl0, bl1, bl2, bl3, smem_u32(&stage[G_BL + rn * GSTR + ks * 16 + ko]));
                MMA_BF16(at[2 * np],     ah[ks], bh0, bh1);
                MMA_BF16(at[2 * np],     ah[ks], bl0, bl1);
                MMA_BF16(at[2 * np],     al[ks], bh0, bh1);
                MMA_BF16(at[2 * np + 1], ah[ks], bh2, bh3);
                MMA_BF16(at[2 * np + 1], ah[ks], bl2, bl3);
                MMA_BF16(at[2 * np + 1], al[ks], bh2, bh3);
            }
        }

        __syncthreads();
        if (ki + 2 < NK)
            gemm_issue(gst[ki & 1], Ah, Al, Bh, Bl, m0, n0, (ki + 2) * 64, K, tid);
        CP_COMMIT;
    }

    const int gr0 = m0 + row0 + tr, gr1 = gr0 + 8;
    #pragma unroll
    for (int n = 0; n < 16; n++) {
        int col = n0 + n * 8 + tc * 2;
        float b0 = bias ? bias[col] : 0.f;
        float b1 = bias ? bias[col + 1] : 0.f;
        *(float2*)&C[(size_t)gr0 * N + col] = make_float2(at[n][0] + b0, at[n][1] + b1);
        *(float2*)&C[(size_t)gr1 * N + col] = make_float2(at[n][2] + b0, at[n][3] + b1);
    }
}

// ---------------- prep kernels ----------------
__global__ void h_split_kernel(const float* __restrict__ h)
{
    int v = blockIdx.x * blockDim.x + threadIdx.x;
    float4 a = ((const float4*)h)[v];
    __nv_bfloat16 h0 = __float2bfloat16(a.x), h1 = __float2bfloat16(a.y);
    __nv_bfloat16 h2 = __float2bfloat16(a.z), h3 = __float2bfloat16(a.w);
    *(uint2*)&g_hh[4 * v] = make_uint2(pack_bf(h0, h1), pack_bf(h2, h3));
    *(uint2*)&g_hl[4 * v] = make_uint2(
        pack_bf(__float2bfloat16(a.x - __bfloat162float(h0)),
                __float2bfloat16(a.y - __bfloat162float(h1))),
        pack_bf(__float2bfloat16(a.z - __bfloat162float(h2)),
                __float2bfloat16(a.w - __bfloat162float(h3))));
}

struct WEnt { const float* src; int N, row_off, Kd, start, count, dst; float scale; };
struct WAll { WEnt w[9]; int total; };

__global__ void prep_weights_kernel(WAll a)
{
    int idx = blockIdx.x * blockDim.x + threadIdx.x;
    if (idx >= a.total) return;
    #pragma unroll
    for (int e = 0; e < 9; e++) {
        if (idx >= a.w[e].start && idx < a.w[e].start + a.w[e].count) {
            int li = idx - a.w[e].start;
            int k = li / a.w[e].N, n = li % a.w[e].N;
            float v = a.w[e].src[li] * a.w[e].scale;
            __nv_bfloat16 hi = __float2bfloat16(v);
            __nv_bfloat16 lo = __float2bfloat16(v - __bfloat162float(hi));
            size_t o = (size_t)(a.w[e].row_off + n) * a.w[e].Kd + k;
            if (a.w[e].dst == 0)      { g_Wp_h[o] = hi; g_Wp_l[o] = lo; }
            else if (a.w[e].dst == 1) { g_Wi_h[o] = hi; g_Wi_l[o] = lo; }
            else                      { g_Wh_h[o] = hi; g_Wh_l[o] = lo; }
            return;
        }
    }
}

__global__ void bias_cat_kernel(const float* b_msg, const float* b_key, const float* b_qry,
                                const float* bi_r, const float* bi_z, const float* bi_n)
{
    int i = threadIdx.x;
    if (i < 128)      g_bias_p[i] = b_msg[i];
    else if (i < 192) g_bias_p[i] = b_key[i - 128];
    else if (i < 256) g_bias_p[i] = 0.125f * b_qry[i - 192];
    if (i < 256)      g_bias_i[i] = bi_r[i];
    else if (i < 512) g_bias_i[i] = bi_z[i - 256];
    else if (i < 768) g_bias_i[i] = bi_n[i - 512];
}

__global__ void split_qk_kernel()
{
    int i = blockIdx.x * blockDim.x + threadIdx.x;
    int row = i >> 6, c = i & 63;
    float k = g_qkm[(size_t)row * 256 + 128 + c];
    __nv_bfloat16 kh = __float2bfloat16(k);
    g_kh[i] = kh; g_kl[i] = __float2bfloat16(k - __bfloat162float(kh));
    float q = g_qkm[(size_t)row * 256 + 192 + c];
    __nv_bfloat16 qh = __float2bfloat16(q);
    g_qh[i] = qh; g_ql[i] = __float2bfloat16(q - __bfloat162float(qh));
}

__global__ void msgT_split_kernel()
{
    __shared__ float t[32][33];
    int n0 = blockIdx.x * 32, m0 = blockIdx.y * 32;
    #pragma unroll
    for (int i = threadIdx.y; i < 32; i += 8)
        t[i][threadIdx.x] = g_qkm[(size_t)(n0 + i) * 256 + m0 + threadIdx.x];
    __syncthreads();
    #pragma unroll
    for (int i = threadIdx.y; i < 32; i += 8) {
        float v = t[threadIdx.x][i];
        __nv_bfloat16 hi = __float2bfloat16(v);
        size_t o = (size_t)(m0 + i) * N_AGENTS + n0 + threadIdx.x;
        g_mTh[o] = hi;
        g_mTl[o] = __float2bfloat16(v - __bfloat162float(hi));
    }
}

// ---------------- normalization / epilogue kernels ----------------
__global__ void inv_S_kernel()
{
    int i = blockIdx.x * blockDim.x + threadIdx.x;
    g_S[i] = 1.0f / (g_S_part[i] + g_S_part[N_AGENTS + i]);
}

__global__ void norm_attended_kernel()
{
    int v = blockIdx.x * blockDim.x + threadIdx.x;
    float inv = g_S[v >> 5];
    const size_t stride = (size_t)N_AGENTS * MSG / 4;
    float4 a = ((const float4*)g_att_part)[v];
    float4 b = ((const float4*)g_att_part)[v + stride];
    float4 o = make_float4((a.x + b.x) * inv, (a.y + b.y) * inv,
                           (a.z + b.z) * inv, (a.w + b.w) * inv);
    __nv_bfloat16 h0 = __float2bfloat16(o.x), h1 = __float2bfloat16(o.y);
    __nv_bfloat16 h2 = __float2bfloat16(o.z), h3 = __float2bfloat16(o.w);
    *(uint2*)&g_ath[4 * v] = make_uint2(pack_bf(h0, h1), pack_bf(h2, h3));
    *(uint2*)&g_atl[4 * v] = make_uint2(
        pack_bf(__float2bfloat16(o.x - __bfloat162float(h0)),
                __float2bfloat16(o.y - __bfloat162float(h1))),
        pack_bf(__float2bfloat16(o.z - __bfloat162float(h2)),
                __float2bfloat16(o.w - __bfloat162float(h3))));
}

__global__ void norm_attn_kernel(float* __restrict__ E)
{
    int v = blockIdx.x * blockDim.x + threadIdx.x;
    float inv = g_S[v >> 11];
    float4 a = ((const float4*)E)[v];
    a.x *= inv; a.y *= inv; a.z *= inv; a.w *= inv;
    ((float4*)E)[v] = a;
}

__device__ __forceinline__ float sigm(float x) { return 1.f / (1.f + __expf(-x)); }

__global__ void gru_final_kernel(const float* __restrict__ h,
                                 const float* __restrict__ bh_n,
                                 float* __restrict__ out)
{
    int v = blockIdx.x * blockDim.x + threadIdx.x;
    int row = v >> 6, c4 = (v & 63) * 4;
    const float* GA = g_GA + (size_t)row * 768;
    const float* GB = g_GB + (size_t)row * 768;
    float4 gar = *(const float4*)&GA[c4];
    float4 gaz = *(const float4*)&GA[256 + c4];
    float4 gan = *(const float4*)&GA[512 + c4];
    float4 gbr = *(const float4*)&GB[c4];
    float4 gbz = *(const float4*)&GB[256 + c4];
    float4 gbn = *(const float4*)&GB[512 + c4];
    float4 bn  = *(const float4*)&bh_n[c4];
    float4 hh  = ((const float4*)h)[v];
    float4 o;
    { float r = sigm(gar.x + gbr.x), z = sigm(gaz.x + gbz.x);
      float n = tanhf(gan.x + r * (gbn.x + bn.x)); o.x = (1.f - z) * n + z * hh.x; }
    { float r = sigm(gar.y + gbr.y), z = sigm(gaz.y + gbz.y);
      float n = tanhf(gan.y + r * (gbn.y + bn.y)); o.y = (1.f - z) * n + z * hh.y; }
    { float r = sigm(gar.z + gbr.z), z = sigm(gaz.z + gbz.z);
      float n = tanhf(gan.z + r * (gbn.z + bn.z)); o.z = (1.f - z) * n + z * hh.z; }
    { float r = sigm(gar.w + gbr.w), z = sigm(gaz.w + gbz.w);
      float n = tanhf(gan.w + r * (gbn.w + bn.w)); o.w = (1.f - z) * n + z * hh.w; }
    ((float4*)out)[v] = o;
}

// ---------------- launch ----------------
extern "C" void kernel_launch(void* const* d_in, const int* in_sizes, int n_in,
                              void* d_out, int out_size)
{
    const float* h     = (const float*)d_in[0];
    const float* W_msg = (const float*)d_in[1];
    const float* b_msg = (const float*)d_in[2];
    const float* W_key = (const float*)d_in[3];
    const float* b_key = (const float*)d_in[4];
    const float* W_qry = (const float*)d_in[5];
    const float* b_qry = (const float*)d_in[6];
    const float* Wi_r  = (const float*)d_in[7];
    const float* bi_r  = (const float*)d_in[8];
    const float* Wi_z  = (const float*)d_in[9];
    const float* bi_z  = (const float*)d_in[10];
    const float* Wi_n  = (const float*)d_in[11];
    const float* bi_n  = (const float*)d_in[12];
    const float* Wh_r  = (const float*)d_in[13];
    const float* Wh_z  = (const float*)d_in[14];
    const float* Wh_n  = (const float*)d_in[15];
    const float* bh_n  = (const float*)d_in[16];

    float* out    = (float*)d_out;
    float* h_new  = out;
    float* attn   = out + (size_t)N_AGENTS * HIDDEN;

    float *p_qkm, *p_GA, *p_GB, *p_bias_p, *p_bias_i;
    __nv_bfloat16 *p_hh, *p_hl, *p_ath, *p_atl;
    __nv_bfloat16 *p_Wp_h, *p_Wp_l, *p_Wi_h, *p_Wi_l, *p_Wh_h, *p_Wh_l;
    cudaGetSymbolAddress((void**)&p_qkm, g_qkm);
    cudaGetSymbolAddress((void**)&p_GA, g_GA);
    cudaGetSymbolAddress((void**)&p_GB, g_GB);
    cudaGetSymbolAddress((void**)&p_bias_p, g_bias_p);
    cudaGetSymbolAddress((void**)&p_bias_i, g_bias_i);
    cudaGetSymbolAddress((void**)&p_hh, g_hh);
    cudaGetSymbolAddress((void**)&p_hl, g_hl);
    cudaGetSymbolAddress((void**)&p_ath, g_ath);
    cudaGetSymbolAddress((void**)&p_atl, g_atl);
    cudaGetSymbolAddress((void**)&p_Wp_h, g_Wp_h);
    cudaGetSymbolAddress((void**)&p_Wp_l, g_Wp_l);
    cudaGetSymbolAddress((void**)&p_Wi_h, g_Wi_h);
    cudaGetSymbolAddress((void**)&p_Wi_l, g_Wi_l);
    cudaGetSymbolAddress((void**)&p_Wh_h, g_Wh_h);
    cudaGetSymbolAddress((void**)&p_Wh_l, g_Wh_l);

    cudaFuncSetAttribute(attn_mma_kernel, cudaFuncAttributeMaxDynamicSharedMemorySize, ATTN_SMEM);
    cudaFuncSetAttribute(gemm_tc, cudaFuncAttributeMaxDynamicSharedMemorySize, GEMM_SMEM);

    // combined weight prep (one launch for all 9 transpose/split jobs)
    WAll wa;
    int off = 0;
    auto add = [&](int e, const float* src, int K, int N, int row_off, int Kd, int dst, float sc) {
        wa.w[e] = WEnt{src, N, row_off, Kd, off, K * N, dst, sc};
        off += K * N;
    };
    add(0, W_msg, 256, 128, 0,   256, 0, 1.0f);
    add(1, W_key, 256, 64,  128, 256, 0, 1.0f);
    add(2, W_qry, 256, 64,  192, 256, 0, 0.125f);
    add(3, Wi_r,  128, 256, 0,   128, 1, 1.0f);
    add(4, Wi_z,  128, 256, 256, 128, 1, 1.0f);
    add(5, Wi_n,  128, 256, 512, 128, 1, 1.0f);
    add(6, Wh_r,  256, 256, 0,   256, 2, 1.0f);
    add(7, Wh_z,  256, 256, 256, 256, 2, 1.0f);
    add(8, Wh_n,  256, 256, 512, 256, 2, 1.0f);
    wa.total = off;

    h_split_kernel<<<(N_AGENTS * HIDDEN / 4) / 256, 256>>>(h);
    bias_cat_kernel<<<1, 1024>>>(b_msg, b_key, b_qry, bi_r, bi_z, bi_n);
    prep_weights_kernel<<<(wa.total + 255) / 256, 256>>>(wa);

    // fused projection: qkm = h @ [W_msg | W_key | 0.125*W_qry] + bias
    gemm_tc<<<dim3(2, N_AGENTS / 128), 256, GEMM_SMEM>>>(
        p_hh, p_hl, p_Wp_h, p_Wp_l, p_bias_p, p_qkm, 256, 256);
    split_qk_kernel<<<(N_AGENTS * KEY) / 256, 256>>>();
    msgT_split_kernel<<<dim3(N_AGENTS / 32, MSG / 32), dim3(32, 8)>>>();

    // fused tensor-core attention (double-buffered)
    attn_mma_kernel<<<dim3(N_AGENTS / 128, NSPLIT), 256, ATTN_SMEM>>>(attn);

    inv_S_kernel<<<N_AGENTS / 256, 256>>>();
    norm_attended_kernel<<<(N_AGENTS * MSG / 4) / 256, 256>>>();
    norm_attn_kernel<<<(int)(((size_t)N_AGENTS * N_AGENTS / 4) / 256), 256>>>(attn);

    // GRU gates
    gemm_tc<<<dim3(6, N_AGENTS / 128), 256, GEMM_SMEM>>>(
        p_ath, p_atl, p_Wi_h, p_Wi_l, p_bias_i, p_GA, 128, 768);
    gemm_tc<<<dim3(6, N_AGENTS / 128), 256, GEMM_SMEM>>>(
        p_hh, p_hl, p_Wh_h, p_Wh_l, nullptr, p_GB, 256, 768);

    gru_final_kernel<<<(N_AGENTS * HIDDEN / 4) / 256, 256>>>(h, bh_n, h_new);
}

// round 8
// speedup vs baseline: 10.0429x; 1.1092x over previous
#include <cuda_runtime.h>
#include <cuda_bf16.h>
#include <cstddef>
#include <cstdint>

#define N_AGENTS 8192
#define HIDDEN   256
#define MSG      128
#define KEY      64
#define NSPLIT   2
#define COLS_PER_SPLIT (N_AGENTS / NSPLIT)   // 4096
#define NT (COLS_PER_SPLIT / 128)            // 32 j-tiles per block

// ---------------- scratch (no allocations allowed) ----------------
__device__ float g_qkm[N_AGENTS * 256];              // msg|key|qry fused projection
__device__ float g_S  [N_AGENTS];
__device__ float g_S_part[NSPLIT * N_AGENTS];
__device__ float g_att_part[NSPLIT * N_AGENTS * MSG];
__device__ float g_GA[N_AGENTS * 768];
__device__ float g_GB[N_AGENTS * 768];
__device__ float g_bias_p[256];
__device__ float g_bias_i[768];

// bf16 hi/lo splits
__device__ __align__(16) __nv_bfloat16 g_kh[N_AGENTS * KEY];
__device__ __align__(16) __nv_bfloat16 g_kl[N_AGENTS * KEY];
__device__ __align__(16) __nv_bfloat16 g_qh[N_AGENTS * KEY];   // prescaled by 1/8
__device__ __align__(16) __nv_bfloat16 g_ql[N_AGENTS * KEY];
__device__ __align__(16) __nv_bfloat16 g_mTh[MSG * N_AGENTS];
__device__ __align__(16) __nv_bfloat16 g_mTl[MSG * N_AGENTS];
__device__ __align__(16) __nv_bfloat16 g_hh[N_AGENTS * HIDDEN];
__device__ __align__(16) __nv_bfloat16 g_hl[N_AGENTS * HIDDEN];
__device__ __align__(16) __nv_bfloat16 g_ath[N_AGENTS * MSG];
__device__ __align__(16) __nv_bfloat16 g_atl[N_AGENTS * MSG];
__device__ __align__(16) __nv_bfloat16 g_Wp_h[256 * 256];
__device__ __align__(16) __nv_bfloat16 g_Wp_l[256 * 256];
__device__ __align__(16) __nv_bfloat16 g_Wi_h[768 * 128];
__device__ __align__(16) __nv_bfloat16 g_Wi_l[768 * 128];
__device__ __align__(16) __nv_bfloat16 g_Wh_h[768 * 256];
__device__ __align__(16) __nv_bfloat16 g_Wh_l[768 * 256];

// ---------------- PTX helpers (compute_103-safe) ----------------
__device__ __forceinline__ uint32_t smem_u32(const void* p) {
    uint32_t a;
    asm("{ .reg .u64 t; cvta.to.shared.u64 t, %1; cvt.u32.u64 %0, t; }" : "=r"(a) : "l"(p));
    return a;
}

#define LDSM_X4(r0, r1, r2, r3, addr) \
    asm volatile("ldmatrix.sync.aligned.m8n8.x4.shared.b16 {%0,%1,%2,%3}, [%4];" \
                 : "=r"(r0), "=r"(r1), "=r"(r2), "=r"(r3) : "r"(addr))

#define MMA_BF16(C, A, B0, B1) \
    asm volatile("mma.sync.aligned.m16n8k16.row.col.f32.bf16.bf16.f32 " \
                 "{%0,%1,%2,%3}, {%4,%5,%6,%7}, {%8,%9}, {%0,%1,%2,%3};" \
                 : "+f"((C)[0]), "+f"((C)[1]), "+f"((C)[2]), "+f"((C)[3]) \
                 : "r"((A)[0]), "r"((A)[1]), "r"((A)[2]), "r"((A)[3]), \
                   "r"(B0), "r"(B1))

#define CP16(smaddr, gptr) \
    asm volatile("cp.async.cg.shared.global [%0], [%1], 16;" :: "r"(smaddr), "l"(gptr) : "memory")
#define CP_COMMIT asm volatile("cp.async.commit_group;" ::: "memory")
#define CP_WAIT1  asm volatile("cp.async.wait_group 1;" ::: "memory")

__device__ __forceinline__ uint32_t pack_bf(__nv_bfloat16 a, __nv_bfloat16 b) {
    return (uint32_t)__bfloat16_as_ushort(a) | ((uint32_t)__bfloat16_as_ushort(b) << 16);
}

// ---------------- attention smem layout (2 pipeline stages) ----------------
#define KSTR 72    // 144 B rows (16B-aligned)
#define MSTR 136   // 272 B rows
#define S_KL (128 * KSTR)
#define S_MH (2 * 128 * KSTR)
#define S_ML (S_MH + 128 * MSTR)
#define STAGE_ELEMS (2 * 128 * KSTR + 2 * 128 * MSTR)   // 53248 bf16
#define ATTN_SMEM (2 * STAGE_ELEMS * 2)                 // 212992 bytes

__device__ __forceinline__ void issue_tile(__nv_bfloat16* stage, size_t j0, int tid) {
    __nv_bfloat16* Kh = stage;
    __nv_bfloat16* Kl = stage + S_KL;
    __nv_bfloat16* Mh = stage + S_MH;
    __nv_bfloat16* Ml = stage + S_ML;
    #pragma unroll
    for (int it = 0; it < 4; it++) {
        int idx = tid + it * 256;
        int r = idx >> 3, ch = idx & 7;
        CP16(smem_u32(&Kh[r * KSTR + ch * 8]), &g_kh[(j0 + r) * KEY + ch * 8]);
        CP16(smem_u32(&Kl[r * KSTR + ch * 8]), &g_kl[(j0 + r) * KEY + ch * 8]);
    }
    #pragma unroll
    for (int it = 0; it < 8; it++) {
        int idx = tid + it * 256;
        int c = idx >> 4, ch = idx & 15;
        CP16(smem_u32(&Mh[c * MSTR + ch * 8]), &g_mTh[(size_t)c * N_AGENTS + j0 + ch * 8]);
        CP16(smem_u32(&Ml[c * MSTR + ch * 8]), &g_mTl[(size_t)c * N_AGENTS + j0 + ch * 8]);
    }
}

// ---------------- fused attention: mma.sync, chain-broken scheduling ----------------
__global__ __launch_bounds__(256, 1) void attn_mma_kernel(float* __restrict__ E_out)
{
    extern __shared__ __nv_bfloat16 sm[];
    __nv_bfloat16* st0 = sm;
    __nv_bfloat16* st1 = sm + STAGE_ELEMS;

    const int tid  = threadIdx.x;
    const int w    = tid >> 5, lane = tid & 31;
    const int tr   = lane >> 2;
    const int tc   = lane & 3;
    const int row0 = w * 16;
    const int i0    = blockIdx.x * 128;
    const int jbase = blockIdx.y * COLS_PER_SPLIT;

    // ---- stage Q (hi/lo) into stage0 K buffers, extract persistent fragments ----
    #pragma unroll
    for (int it = 0; it < 4; it++) {
        int idx = tid + it * 256;
        int r = idx >> 3, ch = idx & 7;
        *(uint4*)&st0[r * KSTR + ch * 8] =
            *(const uint4*)&g_qh[(size_t)(i0 + r) * KEY + ch * 8];
        *(uint4*)&st0[S_KL + r * KSTR + ch * 8] =
            *(const uint4*)&g_ql[(size_t)(i0 + r) * KEY + ch * 8];
    }
    __syncthreads();

    uint32_t qh[4][4], ql[4][4];
    {
        int octet = lane >> 3;
        int rr = row0 + (octet & 1) * 8 + (lane & 7);
        int kk = (octet >> 1) * 8;
        #pragma unroll
        for (int ks = 0; ks < 4; ks++) {
            LDSM_X4(qh[ks][0], qh[ks][1], qh[ks][2], qh[ks][3],
                    smem_u32(&st0[rr * KSTR + ks * 16 + kk]));
            LDSM_X4(ql[ks][0], ql[ks][1], ql[ks][2], ql[ks][3],
                    smem_u32(&st0[S_KL + rr * KSTR + ks * 16 + kk]));
        }
    }
    __syncthreads();

    // ---- pipeline prologue ----
    issue_tile(st0, (size_t)jbase, tid);       CP_COMMIT;
    issue_tile(st1, (size_t)jbase + 128, tid); CP_COMMIT;

    float at[16][4];
    #pragma unroll
    for (int n = 0; n < 16; n++)
        #pragma unroll
        for (int q = 0; q < 4; q++) at[n][q] = 0.f;
    float rs0 = 0.f, rs1 = 0.f;

    const int gr0 = i0 + row0 + tr;
    const int gr1 = gr0 + 8;

    for (int t = 0; t < NT; t++) {
        CP_WAIT1;
        __syncthreads();
        __nv_bfloat16* stage = (t & 1) ? st1 : st0;
        __nv_bfloat16* Kh = stage;
        __nv_bfloat16* Kl = stage + S_KL;
        __nv_bfloat16* Mh = stage + S_MH;
        __nv_bfloat16* Ml = stage + S_ML;
        const int jt = t * 128;

        // ---- scores: 3 independent accumulator chains per n-tile ----
        float cs[16][4];
        #pragma unroll
        for (int n = 0; n < 16; n++) {
            int rn = n * 8 + (lane & 7);
            int ko = (lane >> 3) * 8;
            uint32_t bh[8], bl[8];
            LDSM_X4(bh[0], bh[1], bh[2], bh[3], smem_u32(&Kh[rn * KSTR + ko]));
            LDSM_X4(bh[4], bh[5], bh[6], bh[7], smem_u32(&Kh[rn * KSTR + 32 + ko]));
            LDSM_X4(bl[0], bl[1], bl[2], bl[3], smem_u32(&Kl[rn * KSTR + ko]));
            LDSM_X4(bl[4], bl[5], bl[6], bl[7], smem_u32(&Kl[rn * KSTR + 32 + ko]));
            float c1[4] = {0.f, 0.f, 0.f, 0.f};
            float c2[4] = {0.f, 0.f, 0.f, 0.f};
            float c3[4] = {0.f, 0.f, 0.f, 0.f};
            #pragma unroll
            for (int ks = 0; ks < 4; ks++) {
                MMA_BF16(c1, qh[ks], bh[ks * 2], bh[ks * 2 + 1]);
                MMA_BF16(c2, qh[ks], bl[ks * 2], bl[ks * 2 + 1]);
                MMA_BF16(c3, ql[ks], bh[ks * 2], bh[ks * 2 + 1]);
            }
            #pragma unroll
            for (int q = 0; q < 4; q++) cs[n][q] = c1[q] + c2[q] + c3[q];
        }

        // ---- epilogue: clip, exp, diag, rowsum, write unnormalized E ----
        #pragma unroll
        for (int n = 0; n < 16; n++) {
            int gc = jbase + jt + n * 8 + tc * 2;
            float e0 = __expf(fminf(fmaxf(cs[n][0], -20.f), 20.f));
            float e1 = __expf(fminf(fmaxf(cs[n][1], -20.f), 20.f));
            float e2 = __expf(fminf(fmaxf(cs[n][2], -20.f), 20.f));
            float e3 = __expf(fminf(fmaxf(cs[n][3], -20.f), 20.f));
            if (gr0 == gc)     e0 = 0.f;
            if (gr0 == gc + 1) e1 = 0.f;
            if (gr1 == gc)     e2 = 0.f;
            if (gr1 == gc + 1) e3 = 0.f;
            rs0 += e0 + e1;
            rs1 += e2 + e3;
            cs[n][0] = e0; cs[n][1] = e1; cs[n][2] = e2; cs[n][3] = e3;
            *(float2*)&E_out[(size_t)gr0 * N_AGENTS + gc] = make_float2(e0, e1);
            *(float2*)&E_out[(size_t)gr1 * N_AGENTS + gc] = make_float2(e2, e3);
        }

        // ---- attended: 4-wide n groups, product-major (distance-4 chains) ----
        #pragma unroll
        for (int kp = 0; kp < 8; kp++) {
            uint32_t eh[4], el[4];
            {
                float s00 = cs[2 * kp][0],     s01 = cs[2 * kp][1];
                float s10 = cs[2 * kp][2],     s11 = cs[2 * kp][3];
                float s20 = cs[2 * kp + 1][0], s21 = cs[2 * kp + 1][1];
                float s30 = cs[2 * kp + 1][2], s31 = cs[2 * kp + 1][3];
                __nv_bfloat16 h00 = __float2bfloat16(s00), h01 = __float2bfloat16(s01);
                __nv_bfloat16 h10 = __float2bfloat16(s10), h11 = __float2bfloat16(s11);
                __nv_bfloat16 h20 = __float2bfloat16(s20), h21 = __float2bfloat16(s21);
                __nv_bfloat16 h30 = __float2bfloat16(s30), h31 = __float2bfloat16(s31);
                eh[0] = pack_bf(h00, h01); eh[1] = pack_bf(h10, h11);
                eh[2] = pack_bf(h20, h21); eh[3] = pack_bf(h30, h31);
                el[0] = pack_bf(__float2bfloat16(s00 - __bfloat162float(h00)),
                                __float2bfloat16(s01 - __bfloat162float(h01)));
                el[1] = pack_bf(__float2bfloat16(s10 - __bfloat162float(h10)),
                                __float2bfloat16(s11 - __bfloat162float(h11)));
                el[2] = pack_bf(__float2bfloat16(s20 - __bfloat162float(h20)),
                                __float2bfloat16(s21 - __bfloat162float(h21)));
                el[3] = pack_bf(__float2bfloat16(s30 - __bfloat162float(h30)),
                                __float2bfloat16(s31 - __bfloat162float(h31)));
            }
            #pragma unroll
            for (int g = 0; g < 4; g++) {
                // dual-n LDSM_X4: lanes 0-15 -> n-block (4g+?|0), 16-31 -> next n
                int rnA = (4 * g + ((lane >> 4) & 1)) * 8 + (lane & 7);
                int rnB = (4 * g + 2 + ((lane >> 4) & 1)) * 8 + (lane & 7);
                int jo  = kp * 16 + ((lane >> 3) & 1) * 8;
                uint32_t mh[8], ml[8];
                LDSM_X4(mh[0], mh[1], mh[2], mh[3], smem_u32(&Mh[rnA * MSTR + jo]));
                LDSM_X4(mh[4], mh[5], mh[6], mh[7], smem_u32(&Mh[rnB * MSTR + jo]));
                LDSM_X4(ml[0], ml[1], ml[2], ml[3], smem_u32(&Ml[rnA * MSTR + jo]));
                LDSM_X4(ml[4], ml[5], ml[6], ml[7], smem_u32(&Ml[rnB * MSTR + jo]));
                MMA_BF16(at[4 * g + 0], eh, mh[0], mh[1]);
                MMA_BF16(at[4 * g + 1], eh, mh[2], mh[3]);
                MMA_BF16(at[4 * g + 2], eh, mh[4], mh[5]);
                MMA_BF16(at[4 * g + 3], eh, mh[6], mh[7]);
                MMA_BF16(at[4 * g + 0], eh, ml[0], ml[1]);
                MMA_BF16(at[4 * g + 1], eh, ml[2], ml[3]);
                MMA_BF16(at[4 * g + 2], eh, ml[4], ml[5]);
                MMA_BF16(at[4 * g + 3], eh, ml[6], ml[7]);
                MMA_BF16(at[4 * g + 0], el, mh[0], mh[1]);
                MMA_BF16(at[4 * g + 1], el, mh[2], mh[3]);
                MMA_BF16(at[4 * g + 2], el, mh[4], mh[5]);
                MMA_BF16(at[4 * g + 3], el, mh[6], mh[7]);
            }
        }

        __syncthreads();
        if (t + 2 < NT)
            issue_tile((t & 1) ? st1 : st0, (size_t)jbase + (size_t)(t + 2) * 128, tid);
        CP_COMMIT;
    }

    rs0 += __shfl_xor_sync(0xFFFFFFFFu, rs0, 1);
    rs0 += __shfl_xor_sync(0xFFFFFFFFu, rs0, 2);
    rs1 += __shfl_xor_sync(0xFFFFFFFFu, rs1, 1);
    rs1 += __shfl_xor_sync(0xFFFFFFFFu, rs1, 2);
    if (tc == 0) {
        g_S_part[(size_t)blockIdx.y * N_AGENTS + gr0] = rs0;
        g_S_part[(size_t)blockIdx.y * N_AGENTS + gr1] = rs1;
    }

    #pragma unroll
    for (int n = 0; n < 16; n++) {
        size_t b0 = ((size_t)blockIdx.y * N_AGENTS + gr0) * MSG + n * 8 + tc * 2;
        size_t b1 = ((size_t)blockIdx.y * N_AGENTS + gr1) * MSG + n * 8 + tc * 2;
        *(float2*)&g_att_part[b0] = make_float2(at[n][0], at[n][1]);
        *(float2*)&g_att_part[b1] = make_float2(at[n][2], at[n][3]);
    }
}

// ---------------- tensor-core GEMM: C[M,N] = A@B + bias, chain-broken ----------------
#define GSTR 72
#define G_AL (128 * GSTR)
#define G_BH (2 * 128 * GSTR)
#define G_BL (3 * 128 * GSTR)
#define GSTAGE (4 * 128 * GSTR)
#define GEMM_SMEM (2 * GSTAGE * 2)   // 147456 bytes

__device__ __forceinline__ void gemm_issue(
    __nv_bfloat16* stage,
    const __nv_bfloat16* Ah, const __nv_bfloat16* Al,
    const __nv_bfloat16* Bh, const __nv_bfloat16* Bl,
    int m0, int n0, int kc, int K, int tid)
{
    #pragma unroll
    for (int it = 0; it < 4; it++) {
        int idx = tid + it * 256;
        int r = idx >> 3, ch = idx & 7;
        CP16(smem_u32(&stage[r * GSTR + ch * 8]),        &Ah[(size_t)(m0 + r) * K + kc + ch * 8]);
        CP16(smem_u32(&stage[G_AL + r * GSTR + ch * 8]), &Al[(size_t)(m0 + r) * K + kc + ch * 8]);
        CP16(smem_u32(&stage[G_BH + r * GSTR + ch * 8]), &Bh[(size_t)(n0 + r) * K + kc + ch * 8]);
        CP16(smem_u32(&stage[G_BL + r * GSTR + ch * 8]), &Bl[(size_t)(n0 + r) * K + kc + ch * 8]);
    }
}

__global__ __launch_bounds__(256, 1) void gemm_tc(
    const __nv_bfloat16* __restrict__ Ah, const __nv_bfloat16* __restrict__ Al,
    const __nv_bfloat16* __restrict__ Bh, const __nv_bfloat16* __restrict__ Bl,
    const float* __restrict__ bias, float* __restrict__ C, int K, int N)
{
    extern __shared__ __nv_bfloat16 gsm[];
    __nv_bfloat16* gst[2] = { gsm, gsm + GSTAGE };

    const int tid = threadIdx.x, w = tid >> 5, lane = tid & 31;
    const int tr = lane >> 2, tc = lane & 3;
    const int row0 = w * 16;
    const int m0 = blockIdx.y * 128, n0 = blockIdx.x * 128;
    const int NK = K >> 6;

    gemm_issue(gst[0], Ah, Al, Bh, Bl, m0, n0, 0, K, tid);  CP_COMMIT;
    if (NK > 1) gemm_issue(gst[1], Ah, Al, Bh, Bl, m0, n0, 64, K, tid);
    CP_COMMIT;

    float at[16][4];
    #pragma unroll
    for (int n = 0; n < 16; n++)
        #pragma unroll
        for (int q = 0; q < 4; q++) at[n][q] = 0.f;

    for (int ki = 0; ki < NK; ki++) {
        CP_WAIT1;
        __syncthreads();
        __nv_bfloat16* stage = gst[ki & 1];

        uint32_t ah[4][4], al[4][4];
        {
            int octet = lane >> 3;
            int rr = row0 + (octet & 1) * 8 + (lane & 7);
            int kk = (octet >> 1) * 8;
            #pragma unroll
            for (int ks = 0; ks < 4; ks++) {
                LDSM_X4(ah[ks][0], ah[ks][1], ah[ks][2], ah[ks][3],
                        smem_u32(&stage[rr * GSTR + ks * 16 + kk]));
                LDSM_X4(al[ks][0], al[ks][1], al[ks][2], al[ks][3],
                        smem_u32(&stage[G_AL + rr * GSTR + ks * 16 + kk]));
            }
        }
        // 4 outputs in flight, product-major: distance-4 accumulator chains
        #pragma unroll
        for (int npp = 0; npp < 4; npp++) {
            int rnA = npp * 32 + ((lane >> 4) & 1) * 8 + (lane & 7);
            int rnB = npp * 32 + 16 + ((lane >> 4) & 1) * 8 + (lane & 7);
            int ko = ((lane >> 3) & 1) * 8;
            #pragma unroll
            for (int ks = 0; ks < 4; ks++) {
                uint32_t bhA[4], blA[4], bhB[4], blB[4];
                LDSM_X4(bhA[0], bhA[1], bhA[2], bhA[3],
                        smem_u32(&stage[G_BH + rnA * GSTR + ks * 16 + ko]));
                LDSM_X4(blA[0], blA[1], blA[2], blA[3],
                        smem_u32(&stage[G_BL + rnA * GSTR + ks * 16 + ko]));
                LDSM_X4(bhB[0], bhB[1], bhB[2], bhB[3],
                        smem_u32(&stage[G_BH + rnB * GSTR + ks * 16 + ko]));
                LDSM_X4(blB[0], blB[1], blB[2], blB[3],
                        smem_u32(&stage[G_BL + rnB * GSTR + ks * 16 + ko]));
                MMA_BF16(at[4 * npp + 0], ah[ks], bhA[0], bhA[1]);
                MMA_BF16(at[4 * npp + 1], ah[ks], bhA[2], bhA[3]);
                MMA_BF16(at[4 * npp + 2], ah[ks], bhB[0], bhB[1]);
                MMA_BF16(at[4 * npp + 3], ah[ks], bhB[2], bhB[3]);
                MMA_BF16(at[4 * npp + 0], ah[ks], blA[0], blA[1]);
                MMA_BF16(at[4 * npp + 1], ah[ks], blA[2], blA[3]);
                MMA_BF16(at[4 * npp + 2], ah[ks], blB[0], blB[1]);
                MMA_BF16(at[4 * npp + 3], ah[ks], blB[2], blB[3]);
                MMA_BF16(at[4 * npp + 0], al[ks], bhA[0], bhA[1]);
                MMA_BF16(at[4 * npp + 1], al[ks], bhA[2], bhA[3]);
                MMA_BF16(at[4 * npp + 2], al[ks], bhB[0], bhB[1]);
                MMA_BF16(at[4 * npp + 3], al[ks], bhB[2], bhB[3]);
            }
        }

        __syncthreads();
        if (ki + 2 < NK)
            gemm_issue(gst[ki & 1], Ah, Al, Bh, Bl, m0, n0, (ki + 2) * 64, K, tid);
        CP_COMMIT;
    }

    const int gr0 = m0 + row0 + tr, gr1 = gr0 + 8;
    #pragma unroll
    for (int n = 0; n < 16; n++) {
        int col = n0 + n * 8 + tc * 2;
        float b0 = bias ? bias[col] : 0.f;
        float b1 = bias ? bias[col + 1] : 0.f;
        *(float2*)&C[(size_t)gr0 * N + col] = make_float2(at[n][0] + b0, at[n][1] + b1);
        *(float2*)&C[(size_t)gr1 * N + col] = make_float2(at[n][2] + b0, at[n][3] + b1);
    }
}

// ---------------- prep kernels ----------------
__global__ void h_split_kernel(const float* __restrict__ h)
{
    int v = blockIdx.x * blockDim.x + threadIdx.x;
    float4 a = ((const float4*)h)[v];
    __nv_bfloat16 h0 = __float2bfloat16(a.x), h1 = __float2bfloat16(a.y);
    __nv_bfloat16 h2 = __float2bfloat16(a.z), h3 = __float2bfloat16(a.w);
    *(uint2*)&g_hh[4 * v] = make_uint2(pack_bf(h0, h1), pack_bf(h2, h3));
    *(uint2*)&g_hl[4 * v] = make_uint2(
        pack_bf(__float2bfloat16(a.x - __bfloat162float(h0)),
                __float2bfloat16(a.y - __bfloat162float(h1))),
        pack_bf(__float2bfloat16(a.z - __bfloat162float(h2)),
                __float2bfloat16(a.w - __bfloat162float(h3))));
}

struct WEnt { const float* src; int N, row_off, Kd, start, count, dst; float scale; };
struct WAll { WEnt w[9]; int total; };

__global__ void prep_weights_kernel(WAll a)
{
    int idx = blockIdx.x * blockDim.x + threadIdx.x;
    if (idx >= a.total) return;
    #pragma unroll
    for (int e = 0; e < 9; e++) {
        if (idx >= a.w[e].start && idx < a.w[e].start + a.w[e].count) {
            int li = idx - a.w[e].start;
            int k = li / a.w[e].N, n = li % a.w[e].N;
            float v = a.w[e].src[li] * a.w[e].scale;
            __nv_bfloat16 hi = __float2bfloat16(v);
            __nv_bfloat16 lo = __float2bfloat16(v - __bfloat162float(hi));
            size_t o = (size_t)(a.w[e].row_off + n) * a.w[e].Kd + k;
            if (a.w[e].dst == 0)      { g_Wp_h[o] = hi; g_Wp_l[o] = lo; }
            else if (a.w[e].dst == 1) { g_Wi_h[o] = hi; g_Wi_l[o] = lo; }
            else                      { g_Wh_h[o] = hi; g_Wh_l[o] = lo; }
            return;
        }
    }
}

__global__ void bias_cat_kernel(const float* b_msg, const float* b_key, const float* b_qry,
                                const float* bi_r, const float* bi_z, const float* bi_n)
{
    int i = threadIdx.x;
    if (i < 128)      g_bias_p[i] = b_msg[i];
    else if (i < 192) g_bias_p[i] = b_key[i - 128];
    else if (i < 256) g_bias_p[i] = 0.125f * b_qry[i - 192];
    if (i < 256)      g_bias_i[i] = bi_r[i];
    else if (i < 512) g_bias_i[i] = bi_z[i - 256];
    else if (i < 768) g_bias_i[i] = bi_n[i - 512];
}

__global__ void split_qk_kernel()
{
    int i = blockIdx.x * blockDim.x + threadIdx.x;
    int row = i >> 6, c = i & 63;
    float k = g_qkm[(size_t)row * 256 + 128 + c];
    __nv_bfloat16 kh = __float2bfloat16(k);
    g_kh[i] = kh; g_kl[i] = __float2bfloat16(k - __bfloat162float(kh));
    float q = g_qkm[(size_t)row * 256 + 192 + c];
    __nv_bfloat16 qh = __float2bfloat16(q);
    g_qh[i] = qh; g_ql[i] = __float2bfloat16(q - __bfloat162float(qh));
}

__global__ void msgT_split_kernel()
{
    __shared__ float t[32][33];
    int n0 = blockIdx.x * 32, m0 = blockIdx.y * 32;
    #pragma unroll
    for (int i = threadIdx.y; i < 32; i += 8)
        t[i][threadIdx.x] = g_qkm[(size_t)(n0 + i) * 256 + m0 + threadIdx.x];
    __syncthreads();
    #pragma unroll
    for (int i = threadIdx.y; i < 32; i += 8) {
        float v = t[threadIdx.x][i];
        __nv_bfloat16 hi = __float2bfloat16(v);
        size_t o = (size_t)(m0 + i) * N_AGENTS + n0 + threadIdx.x;
        g_mTh[o] = hi;
        g_mTl[o] = __float2bfloat16(v - __bfloat162float(hi));
    }
}

// ---------------- normalization / epilogue kernels ----------------
__global__ void inv_S_kernel()
{
    int i = blockIdx.x * blockDim.x + threadIdx.x;
    g_S[i] = 1.0f / (g_S_part[i] + g_S_part[N_AGENTS + i]);
}

__global__ void norm_attended_kernel()
{
    int v = blockIdx.x * blockDim.x + threadIdx.x;
    float inv = g_S[v >> 5];
    const size_t stride = (size_t)N_AGENTS * MSG / 4;
    float4 a = ((const float4*)g_att_part)[v];
    float4 b = ((const float4*)g_att_part)[v + stride];
    float4 o = make_float4((a.x + b.x) * inv, (a.y + b.y) * inv,
                           (a.z + b.z) * inv, (a.w + b.w) * inv);
    __nv_bfloat16 h0 = __float2bfloat16(o.x), h1 = __float2bfloat16(o.y);
    __nv_bfloat16 h2 = __float2bfloat16(o.z), h3 = __float2bfloat16(o.w);
    *(uint2*)&g_ath[4 * v] = make_uint2(pack_bf(h0, h1), pack_bf(h2, h3));
    *(uint2*)&g_atl[4 * v] = make_uint2(
        pack_bf(__float2bfloat16(o.x - __bfloat162float(h0)),
                __float2bfloat16(o.y - __bfloat162float(h1))),
        pack_bf(__float2bfloat16(o.z - __bfloat162float(h2)),
                __float2bfloat16(o.w - __bfloat162float(h3))));
}

__global__ void norm_attn_kernel(float* __restrict__ E)
{
    int v = blockIdx.x * blockDim.x + threadIdx.x;
    float inv = g_S[v >> 11];
    float4 a = ((const float4*)E)[v];
    a.x *= inv; a.y *= inv; a.z *= inv; a.w *= inv;
    ((float4*)E)[v] = a;
}

__device__ __forceinline__ float sigm(float x) { return 1.f / (1.f + __expf(-x)); }

__global__ void gru_final_kernel(const float* __restrict__ h,
                                 const float* __restrict__ bh_n,
                                 float* __restrict__ out)
{
    int v = blockIdx.x * blockDim.x + threadIdx.x;
    int row = v >> 6, c4 = (v & 63) * 4;
    const float* GA = g_GA + (size_t)row * 768;
    const float* GB = g_GB + (size_t)row * 768;
    float4 gar = *(const float4*)&GA[c4];
    float4 gaz = *(const float4*)&GA[256 + c4];
    float4 gan = *(const float4*)&GA[512 + c4];
    float4 gbr = *(const float4*)&GB[c4];
    float4 gbz = *(const float4*)&GB[256 + c4];
    float4 gbn = *(const float4*)&GB[512 + c4];
    float4 bn  = *(const float4*)&bh_n[c4];
    float4 hh  = ((const float4*)h)[v];
    float4 o;
    { float r = sigm(gar.x + gbr.x), z = sigm(gaz.x + gbz.x);
      float n = tanhf(gan.x + r * (gbn.x + bn.x)); o.x = (1.f - z) * n + z * hh.x; }
    { float r = sigm(gar.y + gbr.y), z = sigm(gaz.y + gbz.y);
      float n = tanhf(gan.y + r * (gbn.y + bn.y)); o.y = (1.f - z) * n + z * hh.y; }
    { float r = sigm(gar.z + gbr.z), z = sigm(gaz.z + gbz.z);
      float n = tanhf(gan.z + r * (gbn.z + bn.z)); o.z = (1.f - z) * n + z * hh.z; }
    { float r = sigm(gar.w + gbr.w), z = sigm(gaz.w + gbz.w);
      float n = tanhf(gan.w + r * (gbn.w + bn.w)); o.w = (1.f - z) * n + z * hh.w; }
    ((float4*)out)[v] = o;
}

// ---------------- launch ----------------
extern "C" void kernel_launch(void* const* d_in, const int* in_sizes, int n_in,
                              void* d_out, int out_size)
{
    const float* h     = (const float*)d_in[0];
    const float* W_msg = (const float*)d_in[1];
    const float* b_msg = (const float*)d_in[2];
    const float* W_key = (const float*)d_in[3];
    const float* b_key = (const float*)d_in[4];
    const float* W_qry = (const float*)d_in[5];
    const float* b_qry = (const float*)d_in[6];
    const float* Wi_r  = (const float*)d_in[7];
    const float* bi_r  = (const float*)d_in[8];
    const float* Wi_z  = (const float*)d_in[9];
    const float* bi_z  = (const float*)d_in[10];
    const float* Wi_n  = (const float*)d_in[11];
    const float* bi_n  = (const float*)d_in[12];
    const float* Wh_r  = (const float*)d_in[13];
    const float* Wh_z  = (const float*)d_in[14];
    const float* Wh_n  = (const float*)d_in[15];
    const float* bh_n  = (const float*)d_in[16];

    float* out    = (float*)d_out;
    float* h_new  = out;
    float* attn   = out + (size_t)N_AGENTS * HIDDEN;

    float *p_qkm, *p_GA, *p_GB, *p_bias_p, *p_bias_i;
    __nv_bfloat16 *p_hh, *p_hl, *p_ath, *p_atl;
    __nv_bfloat16 *p_Wp_h, *p_Wp_l, *p_Wi_h, *p_Wi_l, *p_Wh_h, *p_Wh_l;
    cudaGetSymbolAddress((void**)&p_qkm, g_qkm);
    cudaGetSymbolAddress((void**)&p_GA, g_GA);
    cudaGetSymbolAddress((void**)&p_GB, g_GB);
    cudaGetSymbolAddress((void**)&p_bias_p, g_bias_p);
    cudaGetSymbolAddress((void**)&p_bias_i, g_bias_i);
    cudaGetSymbolAddress((void**)&p_hh, g_hh);
    cudaGetSymbolAddress((void**)&p_hl, g_hl);
    cudaGetSymbolAddress((void**)&p_ath, g_ath);
    cudaGetSymbolAddress((void**)&p_atl, g_atl);
    cudaGetSymbolAddress((void**)&p_Wp_h, g_Wp_h);
    cudaGetSymbolAddress((void**)&p_Wp_l, g_Wp_l);
    cudaGetSymbolAddress((void**)&p_Wi_h, g_Wi_h);
    cudaGetSymbolAddress((void**)&p_Wi_l, g_Wi_l);
    cudaGetSymbolAddress((void**)&p_Wh_h, g_Wh_h);
    cudaGetSymbolAddress((void**)&p_Wh_l, g_Wh_l);

    cudaFuncSetAttribute(attn_mma_kernel, cudaFuncAttributeMaxDynamicSharedMemorySize, ATTN_SMEM);
    cudaFuncSetAttribute(gemm_tc, cudaFuncAttributeMaxDynamicSharedMemorySize, GEMM_SMEM);

    WAll wa;
    int off = 0;
    auto add = [&](int e, const float* src, int K, int N, int row_off, int Kd, int dst, float sc) {
        wa.w[e] = WEnt{src, N, row_off, Kd, off, K * N, dst, sc};
        off += K * N;
    };
    add(0, W_msg, 256, 128, 0,   256, 0, 1.0f);
    add(1, W_key, 256, 64,  128, 256, 0, 1.0f);
    add(2, W_qry, 256, 64,  192, 256, 0, 0.125f);
    add(3, Wi_r,  128, 256, 0,   128, 1, 1.0f);
    add(4, Wi_z,  128, 256, 256, 128, 1, 1.0f);
    add(5, Wi_n,  128, 256, 512, 128, 1, 1.0f);
    add(6, Wh_r,  256, 256, 0,   256, 2, 1.0f);
    add(7, Wh_z,  256, 256, 256, 256, 2, 1.0f);
    add(8, Wh_n,  256, 256, 512, 256, 2, 1.0f);
    wa.total = off;

    h_split_kernel<<<(N_AGENTS * HIDDEN / 4) / 256, 256>>>(h);
    bias_cat_kernel<<<1, 1024>>>(b_msg, b_key, b_qry, bi_r, bi_z, bi_n);
    prep_weights_kernel<<<(wa.total + 255) / 256, 256>>>(wa);

    // fused projection: qkm = h @ [W_msg | W_key | 0.125*W_qry] + bias
    gemm_tc<<<dim3(2, N_AGENTS / 128), 256, GEMM_SMEM>>>(
        p_hh, p_hl, p_Wp_h, p_Wp_l, p_bias_p, p_qkm, 256, 256);
    split_qk_kernel<<<(N_AGENTS * KEY) / 256, 256>>>();
    msgT_split_kernel<<<dim3(N_AGENTS / 32, MSG / 32), dim3(32, 8)>>>();

    // fused tensor-core attention
    attn_mma_kernel<<<dim3(N_AGENTS / 128, NSPLIT), 256, ATTN_SMEM>>>(attn);

    inv_S_kernel<<<N_AGENTS / 256, 256>>>();
    norm_attended_kernel<<<(N_AGENTS * MSG / 4) / 256, 256>>>();
    norm_attn_kernel<<<(int)(((size_t)N_AGENTS * N_AGENTS / 4) / 256), 256>>>(attn);

    // GRU gates
    gemm_tc<<<dim3(6, N_AGENTS / 128), 256, GEMM_SMEM>>>(
        p_ath, p_atl, p_Wi_h, p_Wi_l, p_bias_i, p_GA, 128, 768);
    gemm_tc<<<dim3(6, N_AGENTS / 128), 256, GEMM_SMEM>>>(
        p_hh, p_hl, p_Wh_h, p_Wh_l, nullptr, p_GB, 256, 768);

    gru_final_kernel<<<(N_AGENTS * HIDDEN / 4) / 256, 256>>>(h, bh_n, h_new);
}